// round 12
// baseline (speedup 1.0000x reference)
#include <cuda_runtime.h>
#include <mma.h>
#include <cstdint>
using namespace nvcuda;

// Problem constants (fixed by the reference)
#define BT      4096      // B * T_dec = B * T_enc = 2 * 2048
#define DM      1024      // d_model
#define NHEADS  16
#define DH      64
#define TDEC    2048
#define TENC    2048
#define NB      2

// Scratch (allocation-free)
__device__ float g_Q[BT * DM];
__device__ float g_K[BT * DM];
__device__ float g_V[BT * DM];
__device__ float g_Y[BT * DM];
__device__ float g_Xr[BT * DM];    // tgt, tf32-rounded
__device__ float g_Mr[BT * DM];    // memory, tf32-rounded
__device__ float g_Wq[DM * DM];
__device__ float g_Wk[DM * DM];
__device__ float g_Wv[DM * DM];
__device__ float g_Wo[DM * DM];

// ---------------------------------------------------------------------------
// helpers
// ---------------------------------------------------------------------------
__device__ __forceinline__ void cp_async16(void* smem_dst, const void* gmem_src) {
    unsigned sa = (unsigned)__cvta_generic_to_shared(smem_dst);
    asm volatile("cp.async.cg.shared.global [%0], [%1], 16;\n" :: "r"(sa), "l"(gmem_src));
}
__device__ __forceinline__ void cp_commit() {
    asm volatile("cp.async.commit_group;\n");
}
__device__ __forceinline__ void cp_wait_all() {
    asm volatile("cp.async.wait_group 0;\n");
}
__device__ __forceinline__ float tf32_round(float v) {
    unsigned t;
    asm("cvt.rna.tf32.f32 %0, %1;" : "=r"(t) : "f"(v));
    return __uint_as_float(t);
}
// PTX mma m16n8k8 tf32: D(16x8,f32) += A(16x8) * B(8x8); layouts verified R11.
__device__ __forceinline__ void mma16n8k8(float* c, const uint32_t* a, const uint32_t* b) {
    asm volatile(
        "mma.sync.aligned.m16n8k8.row.col.f32.tf32.tf32.f32 "
        "{%0,%1,%2,%3}, {%4,%5,%6,%7}, {%8,%9}, {%0,%1,%2,%3};\n"
        : "+f"(c[0]), "+f"(c[1]), "+f"(c[2]), "+f"(c[3])
        : "r"(a[0]), "r"(a[1]), "r"(a[2]), "r"(a[3]), "r"(b[0]), "r"(b[1]));
}

// ---------------------------------------------------------------------------
// Fused tf32 pre-round of three tensors (grid-stride, float4)
// ---------------------------------------------------------------------------
__global__ void round3_kernel(const float* __restrict__ s1, float* __restrict__ d1, int n1,
                              const float* __restrict__ s2, float* __restrict__ d2, int n2,
                              const float* __restrict__ s3, float* __restrict__ d3, int n3)
{
    const int total4 = (n1 + n2 + n3) >> 2;
    for (int i = blockIdx.x * blockDim.x + threadIdx.x; i < total4;
         i += gridDim.x * blockDim.x) {
        int idx = i << 2;
        const float* s; float* d;
        if (idx < n1)            { s = s1 + idx; d = d1 + idx; }
        else if (idx < n1 + n2)  { s = s2 + (idx - n1); d = d2 + (idx - n1); }
        else                     { s = s3 + (idx - n1 - n2); d = d3 + (idx - n1 - n2); }
        float4 v = *reinterpret_cast<const float4*>(s);
        v.x = tf32_round(v.x); v.y = tf32_round(v.y);
        v.z = tf32_round(v.z); v.w = tf32_round(v.w);
        *reinterpret_cast<float4*>(d) = v;
    }
}

// ---------------------------------------------------------------------------
// TF32 tiled GEMM, double-buffered cp.async, BK=32, fused bias epilogue.
// (unchanged from R11 passing version)
// ---------------------------------------------------------------------------
#define GLDA 40     // 32 + 8 pad
#define GLDB 136    // 128 + 8 pad
#define GLDC 132    // 128 + 4 pad
#define GEMM_SMEM_FLOATS (2 * 128 * GLDA + 2 * 32 * GLDB)
#define GEMM_SMEM_BYTES  (GEMM_SMEM_FLOATS * 4)

__global__ __launch_bounds__(256, 2) void gemm_tf32_kernel(
    const float* __restrict__ X, const float* __restrict__ W,
    const float* __restrict__ bias, float* __restrict__ C,
    int K, int N, int do_round)
{
    extern __shared__ float sgm[];
    float (*As)[128 * GLDA] = reinterpret_cast<float (*)[128 * GLDA]>(sgm);
    float (*Bs)[32 * GLDB]  = reinterpret_cast<float (*)[32 * GLDB]>(sgm + 2 * 128 * GLDA);
    float* Cs = sgm;

    const int bm = blockIdx.y * 128;
    const int bn = blockIdx.x * 128;
    const int tid = threadIdx.x;
    const int warp = tid >> 5;
    const int wm = warp >> 1;
    const int wn = warp & 1;

    wmma::fragment<wmma::accumulator, 16, 16, 8, float> acc[2][4];
    #pragma unroll
    for (int i = 0; i < 2; i++)
        #pragma unroll
        for (int j = 0; j < 4; j++)
            wmma::fill_fragment(acc[i][j], 0.0f);

    auto load_stage = [&](int s, int k0) {
        #pragma unroll
        for (int i = tid; i < 1024; i += 256) {
            int row = i >> 3, c4 = i & 7;
            cp_async16(&As[s][row * GLDA + c4 * 4],
                       &X[(size_t)(bm + row) * K + k0 + c4 * 4]);
        }
        #pragma unroll
        for (int i = tid; i < 1024; i += 256) {
            int row = i >> 5, c4 = i & 31;
            cp_async16(&Bs[s][row * GLDB + c4 * 4],
                       &W[(size_t)(k0 + row) * N + bn + c4 * 4]);
        }
        cp_commit();
    };

    const int nk = K / 32;
    load_stage(0, 0);

    for (int kt = 0; kt < nk; kt++) {
        cp_wait_all();
        __syncthreads();
        if (kt + 1 < nk) load_stage((kt + 1) & 1, (kt + 1) * 32);
        const int s = kt & 1;

        #pragma unroll
        for (int kk = 0; kk < 32; kk += 8) {
            wmma::fragment<wmma::matrix_a, 16, 16, 8, wmma::precision::tf32, wmma::row_major> afr[2];
            wmma::fragment<wmma::matrix_b, 16, 16, 8, wmma::precision::tf32, wmma::row_major> bfr[4];
            #pragma unroll
            for (int mt = 0; mt < 2; mt++)
                wmma::load_matrix_sync(afr[mt], &As[s][(wm * 32 + mt * 16) * GLDA + kk], GLDA);
            #pragma unroll
            for (int nt = 0; nt < 4; nt++)
                wmma::load_matrix_sync(bfr[nt], &Bs[s][kk * GLDB + wn * 64 + nt * 16], GLDB);
            #pragma unroll
            for (int mt = 0; mt < 2; mt++)
                #pragma unroll
                for (int nt = 0; nt < 4; nt++)
                    wmma::mma_sync(acc[mt][nt], afr[mt], bfr[nt], acc[mt][nt]);
        }
    }

    __syncthreads();
    #pragma unroll
    for (int mt = 0; mt < 2; mt++)
        #pragma unroll
        for (int nt = 0; nt < 4; nt++)
            wmma::store_matrix_sync(
                &Cs[(size_t)(wm * 32 + mt * 16) * GLDC + wn * 64 + nt * 16],
                acc[mt][nt], GLDC, wmma::mem_row_major);
    __syncthreads();

    {
        const int row = tid >> 1;
        const int half = tid & 1;
        const float* src = &Cs[(size_t)row * GLDC + half * 64];
        const float* bsrc = &bias[bn + half * 64];
        float* dst = &C[(size_t)(bm + row) * N + bn + half * 64];
        if (do_round) {
            #pragma unroll
            for (int j = 0; j < 64; j += 4) {
                float4 v;
                v.x = tf32_round(src[j + 0] + bsrc[j + 0]);
                v.y = tf32_round(src[j + 1] + bsrc[j + 1]);
                v.z = tf32_round(src[j + 2] + bsrc[j + 2]);
                v.w = tf32_round(src[j + 3] + bsrc[j + 3]);
                *reinterpret_cast<float4*>(&dst[j]) = v;
            }
        } else {
            #pragma unroll
            for (int j = 0; j < 64; j += 4) {
                float4 v;
                v.x = src[j + 0] + bsrc[j + 0];
                v.y = src[j + 1] + bsrc[j + 1];
                v.z = src[j + 2] + bsrc[j + 2];
                v.w = src[j + 3] + bsrc[j + 3];
                *reinterpret_cast<float4*>(&dst[j]) = v;
            }
        }
    }
}

// ---------------------------------------------------------------------------
// Flash attention v3: warp-owns-full-rows, register S/O/Q, warp-local softmax.
// CTA = 128 Q rows x one (b,h). 8 warps x 16 rows. KC=64 double-buffered.
// One __syncthreads per KV chunk; P reshaped via per-warp smem stripe.
// smem: Ks [2][64x68] | Vs [2][64x72] | Ps [8][16x68] = 104 KB -> 2 CTAs/SM
// ---------------------------------------------------------------------------
#define QT      128
#define KC      64
#define KLD     68    // 64 + 4  (K/P stripes: banks 4g+tg distinct)
#define VLD     72    // 64 + 8  (V stripe: banks 8tg+g distinct)
#define NJT     (TENC / KC)      // 32
#define ATT_KS_FLOATS (2 * KC * KLD)          // 8704
#define ATT_VS_FLOATS (2 * KC * VLD)          // 9216
#define ATT_PS_FLOATS (8 * 16 * KLD)          // 8704
#define ATT_SMEM_BYTES ((ATT_KS_FLOATS + ATT_VS_FLOATS + ATT_PS_FLOATS) * 4)

__global__ __launch_bounds__(256, 2) void attn_kernel(
    const float* __restrict__ Q, const float* __restrict__ K,
    const float* __restrict__ V, float* __restrict__ Y)
{
    extern __shared__ float sm[];
    float* Ks0 = sm;                         // [2][KC x KLD]
    float* Vs0 = Ks0 + ATT_KS_FLOATS;        // [2][KC x VLD]
    float* Ps  = Vs0 + ATT_VS_FLOATS;        // [8][16 x KLD]

    const int bh = blockIdx.y;
    const int b  = bh >> 4;
    const int h  = bh & 15;
    const int q0 = blockIdx.x * QT;
    const int tid = threadIdx.x;
    const int warp = tid >> 5;
    const int lane = tid & 31;
    const int g   = lane >> 2;          // 0..7: row-in-halfgroup / b-frag col
    const int tg  = lane & 3;           // 0..3: thread-in-group / b-frag k row
    const int R0  = warp * 16;          // warp's first Q row in tile
    float* Psw = Ps + warp * 16 * KLD;  // warp-private P stripe
    const float scale = 0.125f;         // 1/sqrt(64); pow2 keeps tf32 exact

    auto prefetch_kv = [&](int s, int jt) {
        float* Ksb = Ks0 + s * KC * KLD;
        float* Vsb = Vs0 + s * KC * VLD;
        const int j0 = jt * KC;
        #pragma unroll
        for (int i = tid; i < 2048; i += 256) {
            if (i < 1024) {
                int row = i >> 4, c4 = i & 15;
                cp_async16(&Ksb[row * KLD + c4 * 4],
                           &K[(size_t)(b * TENC + j0 + row) * DM + h * DH + c4 * 4]);
            } else {
                int j = i - 1024;
                int row = j >> 4, c4 = j & 15;
                cp_async16(&Vsb[row * VLD + c4 * 4],
                           &V[(size_t)(b * TENC + j0 + row) * DM + h * DH + c4 * 4]);
            }
        }
        cp_commit();
    };

    // ---- Q into registers as A-fragments (8 k-tiles x 4 regs), pre-scaled ----
    uint32_t qa[8][4];
    {
        const float* Qb = &Q[(size_t)(b * TDEC + q0 + R0) * DM + h * DH];
        #pragma unroll
        for (int kt = 0; kt < 8; kt++) {
            qa[kt][0] = __float_as_uint(Qb[(size_t)g * DM + 8 * kt + tg] * scale);
            qa[kt][1] = __float_as_uint(Qb[(size_t)(g + 8) * DM + 8 * kt + tg] * scale);
            qa[kt][2] = __float_as_uint(Qb[(size_t)g * DM + 8 * kt + tg + 4] * scale);
            qa[kt][3] = __float_as_uint(Qb[(size_t)(g + 8) * DM + 8 * kt + tg + 4] * scale);
        }
    }

    // O accumulator (16x64 warp tile: 8 n-tiles x 4) + stats, all registers
    float o[8][4];
    #pragma unroll
    for (int nt = 0; nt < 8; nt++)
        #pragma unroll
        for (int e = 0; e < 4; e++) o[nt][e] = 0.0f;
    float m0 = -1e30f, m1 = -1e30f, l0 = 0.0f, l1 = 0.0f;

    prefetch_kv(0, 0);

    for (int jt = 0; jt < NJT; jt++) {
        cp_wait_all();
        __syncthreads();                 // stage jt&1 ready; prior stage reads done
        if (jt + 1 < NJT) prefetch_kv((jt + 1) & 1, jt + 1);
        const int st = jt & 1;
        const float* Ksb = Ks0 + st * KC * KLD;
        const float* Vsb = Vs0 + st * KC * VLD;

        // ---- S = Q @ K^T : 16 x 64 in registers ----
        float s[8][4];
        #pragma unroll
        for (int nt = 0; nt < 8; nt++)
            #pragma unroll
            for (int e = 0; e < 4; e++) s[nt][e] = 0.0f;
        #pragma unroll
        for (int kt = 0; kt < 8; kt++) {
            #pragma unroll
            for (int nt = 0; nt < 8; nt++) {
                uint32_t bb[2];
                const float* Kr = &Ksb[(8 * nt + g) * KLD + 8 * kt + tg];
                bb[0] = __float_as_uint(Kr[0]);
                bb[1] = __float_as_uint(Kr[4]);
                mma16n8k8(s[nt], qa[kt], bb);
            }
        }

        // ---- warp-local online softmax (rows g and g+8) ----
        {
            float mx0 = -1e30f, mx1 = -1e30f;
            #pragma unroll
            for (int nt = 0; nt < 8; nt++) {
                mx0 = fmaxf(mx0, fmaxf(s[nt][0], s[nt][1]));
                mx1 = fmaxf(mx1, fmaxf(s[nt][2], s[nt][3]));
            }
            mx0 = fmaxf(mx0, __shfl_xor_sync(0xffffffffu, mx0, 1));
            mx0 = fmaxf(mx0, __shfl_xor_sync(0xffffffffu, mx0, 2));
            mx1 = fmaxf(mx1, __shfl_xor_sync(0xffffffffu, mx1, 1));
            mx1 = fmaxf(mx1, __shfl_xor_sync(0xffffffffu, mx1, 2));
            float m0n = fmaxf(m0, mx0);
            float m1n = fmaxf(m1, mx1);
            float al0 = __expf(m0 - m0n);
            float al1 = __expf(m1 - m1n);
            float sum0 = 0.0f, sum1 = 0.0f;
            #pragma unroll
            for (int nt = 0; nt < 8; nt++) {
                s[nt][0] = __expf(s[nt][0] - m0n);
                s[nt][1] = __expf(s[nt][1] - m0n);
                s[nt][2] = __expf(s[nt][2] - m1n);
                s[nt][3] = __expf(s[nt][3] - m1n);
                sum0 += s[nt][0] + s[nt][1];
                sum1 += s[nt][2] + s[nt][3];
            }
            sum0 += __shfl_xor_sync(0xffffffffu, sum0, 1);
            sum0 += __shfl_xor_sync(0xffffffffu, sum0, 2);
            sum1 += __shfl_xor_sync(0xffffffffu, sum1, 1);
            sum1 += __shfl_xor_sync(0xffffffffu, sum1, 2);
            m0 = m0n; m1 = m1n;
            l0 = l0 * al0 + sum0;
            l1 = l1 * al1 + sum1;
            #pragma unroll
            for (int nt = 0; nt < 8; nt++) {
                o[nt][0] *= al0; o[nt][1] *= al0;
                o[nt][2] *= al1; o[nt][3] *= al1;
            }
        }

        // ---- P (acc layout) -> warp smem stripe (A layout source) ----
        #pragma unroll
        for (int nt = 0; nt < 8; nt++) {
            float2 p0, p1;
            p0.x = tf32_round(s[nt][0]); p0.y = tf32_round(s[nt][1]);
            p1.x = tf32_round(s[nt][2]); p1.y = tf32_round(s[nt][3]);
            *reinterpret_cast<float2*>(&Psw[g * KLD + 8 * nt + 2 * tg]) = p0;
            *reinterpret_cast<float2*>(&Psw[(g + 8) * KLD + 8 * nt + 2 * tg]) = p1;
        }
        __syncwarp();

        // ---- O += P @ V ----
        #pragma unroll
        for (int kt = 0; kt < 8; kt++) {
            uint32_t a[4];
            const float* Pr = &Psw[g * KLD + 8 * kt + tg];
            a[0] = __float_as_uint(Pr[0]);
            a[1] = __float_as_uint(Pr[8 * KLD]);
            a[2] = __float_as_uint(Pr[4]);
            a[3] = __float_as_uint(Pr[8 * KLD + 4]);
            #pragma unroll
            for (int nt = 0; nt < 8; nt++) {
                uint32_t bb[2];
                const float* Vr = &Vsb[(8 * kt + tg) * VLD + 8 * nt + g];
                bb[0] = __float_as_uint(Vr[0]);
                bb[1] = __float_as_uint(Vr[4 * VLD]);
                mma16n8k8(o[nt], a, bb);
            }
        }
        __syncwarp();   // stripe reuse safe before next jt's P store
    }

    // ---- Epilogue: Y rows R0+g / R0+8+g, tf32-rounded for the O-proj ----
    {
        const float inv0 = 1.0f / l0;
        const float inv1 = 1.0f / l1;
        const size_t row_lo = (size_t)(b * TDEC + q0 + R0 + g) * DM + h * DH;
        const size_t row_hi = row_lo + (size_t)8 * DM;
        #pragma unroll
        for (int nt = 0; nt < 8; nt++) {
            const int c = 8 * nt + 2 * tg;
            float2 vlo, vhi;
            vlo.x = tf32_round(o[nt][0] * inv0);
            vlo.y = tf32_round(o[nt][1] * inv0);
            vhi.x = tf32_round(o[nt][2] * inv1);
            vhi.y = tf32_round(o[nt][3] * inv1);
            *reinterpret_cast<float2*>(&Y[row_lo + c]) = vlo;
            *reinterpret_cast<float2*>(&Y[row_hi + c]) = vhi;
        }
    }
}

// ---------------------------------------------------------------------------
// Launcher.  Launch index 5 = attn_kernel (ncu -s 5 -c 1 profiles it).
// ---------------------------------------------------------------------------
extern "C" void kernel_launch(void* const* d_in, const int* in_sizes, int n_in,
                              void* d_out, int out_size)
{
    const float* tgt    = (const float*)d_in[0];
    const float* memory = (const float*)d_in[1];
    const float* W_q    = (const float*)d_in[2];
    const float* b_q    = (const float*)d_in[3];
    const float* W_k    = (const float*)d_in[4];
    const float* b_k    = (const float*)d_in[5];
    const float* W_v    = (const float*)d_in[6];
    const float* b_v    = (const float*)d_in[7];
    const float* W_o    = (const float*)d_in[8];
    const float* b_o    = (const float*)d_in[9];
    float* out = (float*)d_out;

    float *gQ, *gK, *gV, *gY, *gXr, *gMr, *wq, *wk, *wv, *wo;
    cudaGetSymbolAddress((void**)&gQ, g_Q);
    cudaGetSymbolAddress((void**)&gK, g_K);
    cudaGetSymbolAddress((void**)&gV, g_V);
    cudaGetSymbolAddress((void**)&gY, g_Y);
    cudaGetSymbolAddress((void**)&gXr, g_Xr);
    cudaGetSymbolAddress((void**)&gMr, g_Mr);
    cudaGetSymbolAddress((void**)&wq, g_Wq);
    cudaGetSymbolAddress((void**)&wk, g_Wk);
    cudaGetSymbolAddress((void**)&wv, g_Wv);
    cudaGetSymbolAddress((void**)&wo, g_Wo);

    cudaFuncSetAttribute(gemm_tf32_kernel, cudaFuncAttributeMaxDynamicSharedMemorySize,
                         GEMM_SMEM_BYTES);
    cudaFuncSetAttribute(attn_kernel, cudaFuncAttributeMaxDynamicSharedMemorySize,
                         ATT_SMEM_BYTES);

    const int nact = BT * DM;    // 4M
    const int nw = DM * DM;      // 1M

    // 0,1: pre-round all GEMM operands to tf32
    round3_kernel<<<1184, 256>>>(tgt, gXr, nact, W_q, wq, nw, W_k, wk, nw);
    round3_kernel<<<1184, 256>>>(memory, gMr, nact, W_v, wv, nw, W_o, wo, nw);

    dim3 ggrid(DM / 128, BT / 128);   // (8, 32)
    // 2,3,4: projections with fused bias + tf32 round
    gemm_tf32_kernel<<<ggrid, 256, GEMM_SMEM_BYTES>>>(gXr, wq, b_q, gQ, DM, DM, 1);
    gemm_tf32_kernel<<<ggrid, 256, GEMM_SMEM_BYTES>>>(gMr, wk, b_k, gK, DM, DM, 1);
    gemm_tf32_kernel<<<ggrid, 256, GEMM_SMEM_BYTES>>>(gMr, wv, b_v, gV, DM, DM, 1);
    // 5: attention (profiled launch)
    attn_kernel<<<dim3(TDEC / QT, NB * NHEADS), 256, ATT_SMEM_BYTES>>>(gQ, gK, gV, gY);
    // 6: output projection (no rounding on final output)
    gemm_tf32_kernel<<<ggrid, 256, GEMM_SMEM_BYTES>>>(gY, wo, b_o, out, DM, DM, 0);
}

// round 13
// speedup vs baseline: 3.0359x; 3.0359x over previous
#include <cuda_runtime.h>
#include <cuda_fp16.h>
#include <mma.h>
#include <cstdint>
using namespace nvcuda;

// Problem constants (fixed by the reference)
#define BT      4096      // B * T_dec = B * T_enc = 2 * 2048
#define DM      1024      // d_model
#define NHEADS  16
#define DH      64
#define TDEC    2048
#define TENC    2048
#define NB      2

// Scratch (allocation-free)
__device__ __half g_Qh[BT * DM];
__device__ __half g_Kh[BT * DM];
__device__ __half g_Vh[BT * DM];
__device__ __half g_Yh[BT * DM];
__device__ __half g_Xh[BT * DM];    // tgt, fp16
__device__ __half g_Mh[BT * DM];    // memory, fp16
__device__ __half g_Wqh[DM * DM];
__device__ __half g_Wkh[DM * DM];
__device__ __half g_Wvh[DM * DM];
__device__ __half g_Woh[DM * DM];

// ---------------------------------------------------------------------------
// helpers
// ---------------------------------------------------------------------------
__device__ __forceinline__ void cp_async16(void* smem_dst, const void* gmem_src) {
    unsigned sa = (unsigned)__cvta_generic_to_shared(smem_dst);
    asm volatile("cp.async.cg.shared.global [%0], [%1], 16;\n" :: "r"(sa), "l"(gmem_src));
}
__device__ __forceinline__ void cp_commit() {
    asm volatile("cp.async.commit_group;\n");
}
__device__ __forceinline__ void cp_wait_all() {
    asm volatile("cp.async.wait_group 0;\n");
}
// PTX mma m16n8k16 fp16->fp32. Fragment layouts = generalization of the
// m16n8k8 tf32 layouts verified in R11 (half2 k-pairs instead of single k).
__device__ __forceinline__ void mma16n8k16(float* c, const uint32_t* a, const uint32_t* b) {
    asm volatile(
        "mma.sync.aligned.m16n8k16.row.col.f32.f16.f16.f32 "
        "{%0,%1,%2,%3}, {%4,%5,%6,%7}, {%8,%9}, {%0,%1,%2,%3};\n"
        : "+f"(c[0]), "+f"(c[1]), "+f"(c[2]), "+f"(c[3])
        : "r"(a[0]), "r"(a[1]), "r"(a[2]), "r"(a[3]), "r"(b[0]), "r"(b[1]));
}

// ---------------------------------------------------------------------------
// Fused fp32 -> fp16 conversion of three tensors (grid-stride, float4 in)
// ---------------------------------------------------------------------------
__global__ void convert3_kernel(const float* __restrict__ s1, __half* __restrict__ d1, int n1,
                                const float* __restrict__ s2, __half* __restrict__ d2, int n2,
                                const float* __restrict__ s3, __half* __restrict__ d3, int n3)
{
    const int total4 = (n1 + n2 + n3) >> 2;
    for (int i = blockIdx.x * blockDim.x + threadIdx.x; i < total4;
         i += gridDim.x * blockDim.x) {
        int idx = i << 2;
        const float* s; __half* d;
        if (idx < n1)            { s = s1 + idx; d = d1 + idx; }
        else if (idx < n1 + n2)  { s = s2 + (idx - n1); d = d2 + (idx - n1); }
        else                     { s = s3 + (idx - n1 - n2); d = d3 + (idx - n1 - n2); }
        float4 v = *reinterpret_cast<const float4*>(s);
        __half2 h0 = __floats2half2_rn(v.x, v.y);
        __half2 h1 = __floats2half2_rn(v.z, v.w);
        uint2 u;
        u.x = *reinterpret_cast<uint32_t*>(&h0);
        u.y = *reinterpret_cast<uint32_t*>(&h1);
        *reinterpret_cast<uint2*>(d) = u;
    }
}

// ---------------------------------------------------------------------------
// FP16 tiled GEMM, double-buffered cp.async, BK=32, fused bias epilogue.
// C = X @ W (X: MxK row-major halves, W: KxN row-major halves).
// Tile 128x128, 8 warps (warp tile 32x64). Output: half (out_half) or float.
// ---------------------------------------------------------------------------
#define GLDA 40     // 32 + 8 pad (halves)
#define GLDB 136    // 128 + 8 pad (halves)
#define GLDC 132    // 128 + 4 pad (floats)
#define A_STG (128 * GLDA)              // halves per A stage
#define B_STG (32 * GLDB)               // halves per B stage
#define GEMM_SMEM_BYTES (128 * GLDC * 4)   // 67584 >= stage bytes (37888)

__global__ __launch_bounds__(256, 2) void gemm_fp16_kernel(
    const __half* __restrict__ X, const __half* __restrict__ W,
    const float* __restrict__ bias, void* __restrict__ Cout,
    int K, int N, int out_half)
{
    extern __shared__ char smraw[];
    __half* As = reinterpret_cast<__half*>(smraw);                     // [2][A_STG]
    __half* Bs = reinterpret_cast<__half*>(smraw + 2 * A_STG * 2);     // [2][B_STG]
    float*  Cs = reinterpret_cast<float*>(smraw);                      // epilogue alias

    const int bm = blockIdx.y * 128;
    const int bn = blockIdx.x * 128;
    const int tid = threadIdx.x;
    const int warp = tid >> 5;
    const int wm = warp >> 1;   // 0..3 -> row block of 32
    const int wn = warp & 1;    // 0..1 -> col block of 64

    wmma::fragment<wmma::accumulator, 16, 16, 16, float> acc[2][4];
    #pragma unroll
    for (int i = 0; i < 2; i++)
        #pragma unroll
        for (int j = 0; j < 4; j++)
            wmma::fill_fragment(acc[i][j], 0.0f);

    // stage loader: A 128x32h (512 x 16B), B 32x128h (512 x 16B); 2+2 per thread
    auto load_stage = [&](int s, int k0) {
        #pragma unroll
        for (int i = tid; i < 512; i += 256) {
            int row = i >> 2, c16 = i & 3;
            cp_async16(&As[s * A_STG + row * GLDA + c16 * 8],
                       &X[(size_t)(bm + row) * K + k0 + c16 * 8]);
        }
        #pragma unroll
        for (int i = tid; i < 512; i += 256) {
            int row = i >> 4, c16 = i & 15;
            cp_async16(&Bs[s * B_STG + row * GLDB + c16 * 8],
                       &W[(size_t)(k0 + row) * N + bn + c16 * 8]);
        }
        cp_commit();
    };

    const int nk = K / 32;
    load_stage(0, 0);

    for (int kt = 0; kt < nk; kt++) {
        cp_wait_all();
        __syncthreads();
        if (kt + 1 < nk) load_stage((kt + 1) & 1, (kt + 1) * 32);
        const int s = kt & 1;

        #pragma unroll
        for (int kk = 0; kk < 32; kk += 16) {
            wmma::fragment<wmma::matrix_a, 16, 16, 16, __half, wmma::row_major> afr[2];
            wmma::fragment<wmma::matrix_b, 16, 16, 16, __half, wmma::row_major> bfr[4];
            #pragma unroll
            for (int mt = 0; mt < 2; mt++)
                wmma::load_matrix_sync(afr[mt],
                    &As[s * A_STG + (wm * 32 + mt * 16) * GLDA + kk], GLDA);
            #pragma unroll
            for (int nt = 0; nt < 4; nt++)
                wmma::load_matrix_sync(bfr[nt],
                    &Bs[s * B_STG + kk * GLDB + wn * 64 + nt * 16], GLDB);
            #pragma unroll
            for (int mt = 0; mt < 2; mt++)
                #pragma unroll
                for (int nt = 0; nt < 4; nt++)
                    wmma::mma_sync(acc[mt][nt], afr[mt], bfr[nt], acc[mt][nt]);
        }
    }

    // Epilogue: fragments -> smem (float), then bias -> global (half or float)
    __syncthreads();
    #pragma unroll
    for (int mt = 0; mt < 2; mt++)
        #pragma unroll
        for (int nt = 0; nt < 4; nt++)
            wmma::store_matrix_sync(
                &Cs[(size_t)(wm * 32 + mt * 16) * GLDC + wn * 64 + nt * 16],
                acc[mt][nt], GLDC, wmma::mem_row_major);
    __syncthreads();

    {
        const int row = tid >> 1;          // 2 threads per row
        const int half_ = tid & 1;         // 64 cols each
        const float* src = &Cs[(size_t)row * GLDC + half_ * 64];
        const float* bsrc = &bias[bn + half_ * 64];
        if (out_half) {
            __half* dst = (__half*)Cout + (size_t)(bm + row) * N + bn + half_ * 64;
            #pragma unroll
            for (int j = 0; j < 64; j += 8) {
                uint4 u;
                __half2 h0 = __floats2half2_rn(src[j + 0] + bsrc[j + 0], src[j + 1] + bsrc[j + 1]);
                __half2 h1 = __floats2half2_rn(src[j + 2] + bsrc[j + 2], src[j + 3] + bsrc[j + 3]);
                __half2 h2 = __floats2half2_rn(src[j + 4] + bsrc[j + 4], src[j + 5] + bsrc[j + 5]);
                __half2 h3 = __floats2half2_rn(src[j + 6] + bsrc[j + 6], src[j + 7] + bsrc[j + 7]);
                u.x = *reinterpret_cast<uint32_t*>(&h0);
                u.y = *reinterpret_cast<uint32_t*>(&h1);
                u.z = *reinterpret_cast<uint32_t*>(&h2);
                u.w = *reinterpret_cast<uint32_t*>(&h3);
                *reinterpret_cast<uint4*>(&dst[j]) = u;
            }
        } else {
            float* dst = (float*)Cout + (size_t)(bm + row) * N + bn + half_ * 64;
            #pragma unroll
            for (int j = 0; j < 64; j += 4) {
                float4 v;
                v.x = src[j + 0] + bsrc[j + 0];
                v.y = src[j + 1] + bsrc[j + 1];
                v.z = src[j + 2] + bsrc[j + 2];
                v.w = src[j + 3] + bsrc[j + 3];
                *reinterpret_cast<float4*>(&dst[j]) = v;
            }
        }
    }
}

// ---------------------------------------------------------------------------
// Flash attention (R11-v2 structure, fp16 operands):
//  - S = Q K^T via wmma m16n16k16 (half) -> float smem Ss
//  - softmax on float Ss; P written as half into Ps; alpha/m/l in smem
//  - O += P V via PTX mma m16n8k16, O in registers (layouts proven)
// One block = one (b,h) x 64 query rows, KC=64, double-buffered K/V.
// grid = (TDEC/64, B*NHEADS), 256 threads, 2 CTAs/SM.
// ---------------------------------------------------------------------------
#define KC      64
#define QLDH    72    // halves (Qs/Ps/Ks/Vs pad)
#define SLDF    68    // floats (Ss pad)
// bytes: Ss 64*68*4 | Qs 64*72*2 | Ps 64*72*2 | Ks 2*64*72*2 | Vs 2*64*72*2 | stats 192*4
#define ATT_SS_OFF   0
#define ATT_QS_OFF   (64 * SLDF * 4)                       // 17408
#define ATT_PS_OFF   (ATT_QS_OFF + 64 * QLDH * 2)          // 26624
#define ATT_KS_OFF   (ATT_PS_OFF + 64 * QLDH * 2)          // 35840
#define ATT_VS_OFF   (ATT_KS_OFF + 2 * KC * QLDH * 2)      // 54272
#define ATT_ST_OFF   (ATT_VS_OFF + 2 * KC * QLDH * 2)      // 72704
#define ATT_SMEM_BYTES (ATT_ST_OFF + 192 * 4)              // 73472
#define NJT     (TENC / KC)      // 32

__global__ __launch_bounds__(256, 2) void attn_kernel(
    const __half* __restrict__ Q, const __half* __restrict__ K,
    const __half* __restrict__ V, __half* __restrict__ Y)
{
    extern __shared__ char smraw[];
    float*  Ss  = reinterpret_cast<float*>(smraw + ATT_SS_OFF);   // 64 x SLDF
    __half* Qs  = reinterpret_cast<__half*>(smraw + ATT_QS_OFF);  // 64 x QLDH
    __half* Ps  = reinterpret_cast<__half*>(smraw + ATT_PS_OFF);  // 64 x QLDH
    __half* Ks0 = reinterpret_cast<__half*>(smraw + ATT_KS_OFF);  // [2][KC x QLDH]
    __half* Vs0 = reinterpret_cast<__half*>(smraw + ATT_VS_OFF);  // [2][KC x QLDH]
    float*  m_s = reinterpret_cast<float*>(smraw + ATT_ST_OFF);   // 64
    float*  l_s = m_s + 64;                                       // 64
    float*  a_s = l_s + 64;                                       // 64

    const int bh = blockIdx.y;
    const int b  = bh >> 4;
    const int h  = bh & 15;
    const int q0 = blockIdx.x * 64;
    const int tid = threadIdx.x;
    const int warp = tid >> 5;
    const int lane = tid & 31;
    const int g   = lane >> 2;
    const int tg  = lane & 3;
    const int wm = warp >> 1;           // 0..3 -> 16-row stripe
    const int wn = warp & 1;            // 0..1 -> 32-col half
    const int R0 = wm * 16;
    const int C0 = wn * 32;

    auto prefetch_kv = [&](int s, int jt) {
        __half* Ksb = Ks0 + s * KC * QLDH;
        __half* Vsb = Vs0 + s * KC * QLDH;
        const int j0 = jt * KC;
        #pragma unroll
        for (int i = tid; i < 1024; i += 256) {
            if (i < 512) {
                int row = i >> 3, c16 = i & 7;
                cp_async16(&Ksb[row * QLDH + c16 * 8],
                           &K[(size_t)(b * TENC + j0 + row) * DM + h * DH + c16 * 8]);
            } else {
                int j = i - 512;
                int row = j >> 3, c16 = j & 7;
                cp_async16(&Vsb[row * QLDH + c16 * 8],
                           &V[(size_t)(b * TENC + j0 + row) * DM + h * DH + c16 * 8]);
            }
        }
        cp_commit();
    };

    // Load Q tile (64x64 halves), pre-scaled by 0.125 (exact in fp16)
    {
        const __half2 sc2 = __float2half2_rn(0.125f);
        __half2* Qs2 = reinterpret_cast<__half2*>(Qs);
        const __half2* Qg = reinterpret_cast<const __half2*>(Q);
        #pragma unroll
        for (int i = tid; i < 2048; i += 256) {
            int r = i >> 5, c2 = i & 31;
            __half2 v = Qg[(size_t)(b * TDEC + q0 + r) * (DM / 2) + h * 32 + c2];
            Qs2[r * (QLDH / 2) + c2] = __hmul2(v, sc2);
        }
    }
    if (tid < 64) { m_s[tid] = -1e30f; l_s[tid] = 0.0f; }

    // Register O accumulator: 4 n8-tiles x 4 f32 = 16x32 warp tile
    float o[4][4];
    #pragma unroll
    for (int nt = 0; nt < 4; nt++)
        #pragma unroll
        for (int e = 0; e < 4; e++) o[nt][e] = 0.0f;

    prefetch_kv(0, 0);

    for (int jt = 0; jt < NJT; jt++) {
        cp_wait_all();
        __syncthreads();
        if (jt + 1 < NJT) prefetch_kv((jt + 1) & 1, jt + 1);
        const int st = jt & 1;
        const __half* Ksb = Ks0 + st * KC * QLDH;
        const __half* Vsb = Vs0 + st * KC * QLDH;

        // ---- S = Qs @ Ks^T : 64 x 64, warp tile 16 x 32 (wmma fp16) ----
        {
            wmma::fragment<wmma::accumulator, 16, 16, 16, float> sacc[2];
            wmma::fill_fragment(sacc[0], 0.0f);
            wmma::fill_fragment(sacc[1], 0.0f);
            #pragma unroll
            for (int kk = 0; kk < 64; kk += 16) {
                wmma::fragment<wmma::matrix_a, 16, 16, 16, __half, wmma::row_major> afr;
                wmma::load_matrix_sync(afr, &Qs[R0 * QLDH + kk], QLDH);
                #pragma unroll
                for (int nt = 0; nt < 2; nt++) {
                    wmma::fragment<wmma::matrix_b, 16, 16, 16, __half, wmma::col_major> bfr;
                    wmma::load_matrix_sync(bfr, &Ksb[(C0 + nt * 16) * QLDH + kk], QLDH);
                    wmma::mma_sync(sacc[nt], afr, bfr, sacc[nt]);
                }
            }
            #pragma unroll
            for (int nt = 0; nt < 2; nt++)
                wmma::store_matrix_sync(&Ss[R0 * SLDF + C0 + nt * 16],
                                        sacc[nt], SLDF, wmma::mem_row_major);
        }
        __syncthreads();

        // ---- online softmax: 4 threads/row, 16 strided cols; P -> half Ps ----
        {
            int r = tid >> 2, seg = tid & 3;
            float* Sr = &Ss[r * SLDF];
            __half* Pr = &Ps[r * QLDH];
            float mx = -1e30f;
            #pragma unroll
            for (int c = 0; c < 16; c++) mx = fmaxf(mx, Sr[seg + 4 * c]);
            mx = fmaxf(mx, __shfl_xor_sync(0xffffffffu, mx, 1));
            mx = fmaxf(mx, __shfl_xor_sync(0xffffffffu, mx, 2));
            float mold = m_s[r];
            float mnew = fmaxf(mold, mx);
            float alpha = __expf(mold - mnew);
            float sum = 0.0f;
            #pragma unroll
            for (int c = 0; c < 16; c++) {
                float p = __expf(Sr[seg + 4 * c] - mnew);
                sum += p;
                Pr[seg + 4 * c] = __float2half_rn(p);
            }
            sum += __shfl_xor_sync(0xffffffffu, sum, 1);
            sum += __shfl_xor_sync(0xffffffffu, sum, 2);
            if (seg == 0) {
                m_s[r] = mnew;
                l_s[r] = l_s[r] * alpha + sum;
                a_s[r] = alpha;
            }
        }
        __syncthreads();

        // ---- O = O*alpha + P @ V : PTX mma fp16, O in registers ----
        {
            const float alo = a_s[R0 + g];
            const float ahi = a_s[R0 + 8 + g];
            #pragma unroll
            for (int nt = 0; nt < 4; nt++) {
                o[nt][0] *= alo; o[nt][1] *= alo;
                o[nt][2] *= ahi; o[nt][3] *= ahi;
            }
            #pragma unroll
            for (int k0 = 0; k0 < KC; k0 += 16) {
                uint32_t a[4];
                a[0] = *reinterpret_cast<const uint32_t*>(&Ps[(R0 + g) * QLDH + k0 + 2 * tg]);
                a[1] = *reinterpret_cast<const uint32_t*>(&Ps[(R0 + 8 + g) * QLDH + k0 + 2 * tg]);
                a[2] = *reinterpret_cast<const uint32_t*>(&Ps[(R0 + g) * QLDH + k0 + 2 * tg + 8]);
                a[3] = *reinterpret_cast<const uint32_t*>(&Ps[(R0 + 8 + g) * QLDH + k0 + 2 * tg + 8]);
                #pragma unroll
                for (int nt = 0; nt < 4; nt++) {
                    const int c = C0 + nt * 8 + g;
                    uint32_t bb[2];
                    uint32_t lo0 = (uint32_t)*reinterpret_cast<const unsigned short*>(
                        &Vsb[(k0 + 2 * tg) * QLDH + c]);
                    uint32_t hi0 = (uint32_t)*reinterpret_cast<const unsigned short*>(
                        &Vsb[(k0 + 2 * tg + 1) * QLDH + c]);
                    uint32_t lo1 = (uint32_t)*reinterpret_cast<const unsigned short*>(
                        &Vsb[(k0 + 2 * tg + 8) * QLDH + c]);
                    uint32_t hi1 = (uint32_t)*reinterpret_cast<const unsigned short*>(
                        &Vsb[(k0 + 2 * tg + 9) * QLDH + c]);
                    bb[0] = lo0 | (hi0 << 16);
                    bb[1] = lo1 | (hi1 << 16);
                    mma16n8k16(o[nt], a, bb);
                }
            }
        }
        // next iteration's top barrier protects Ss/Ps/stage reuse
    }
    __syncthreads();

    // Epilogue: Y (half) rows R0+g / R0+8+g, cols C0+8nt+2tg{,+1}
    {
        const float inv_lo = 1.0f / l_s[R0 + g];
        const float inv_hi = 1.0f / l_s[R0 + 8 + g];
        const size_t row_lo = (size_t)(b * TDEC + q0 + R0 + g) * DM + h * DH;
        const size_t row_hi = row_lo + (size_t)8 * DM;
        #pragma unroll
        for (int nt = 0; nt < 4; nt++) {
            const int c = C0 + nt * 8 + 2 * tg;
            __half2 vlo = __floats2half2_rn(o[nt][0] * inv_lo, o[nt][1] * inv_lo);
            __half2 vhi = __floats2half2_rn(o[nt][2] * inv_hi, o[nt][3] * inv_hi);
            *reinterpret_cast<__half2*>(&Y[row_lo + c]) = vlo;
            *reinterpret_cast<__half2*>(&Y[row_hi + c]) = vhi;
        }
    }
}

// ---------------------------------------------------------------------------
// Launcher.  Launch index 5 = attn_kernel.
// ---------------------------------------------------------------------------
extern "C" void kernel_launch(void* const* d_in, const int* in_sizes, int n_in,
                              void* d_out, int out_size)
{
    const float* tgt    = (const float*)d_in[0];
    const float* memory = (const float*)d_in[1];
    const float* W_q    = (const float*)d_in[2];
    const float* b_q    = (const float*)d_in[3];
    const float* W_k    = (const float*)d_in[4];
    const float* b_k    = (const float*)d_in[5];
    const float* W_v    = (const float*)d_in[6];
    const float* b_v    = (const float*)d_in[7];
    const float* W_o    = (const float*)d_in[8];
    const float* b_o    = (const float*)d_in[9];
    float* out = (float*)d_out;

    __half *gQ, *gK, *gV, *gY, *gX, *gM, *wq, *wk, *wv, *wo;
    cudaGetSymbolAddress((void**)&gQ, g_Qh);
    cudaGetSymbolAddress((void**)&gK, g_Kh);
    cudaGetSymbolAddress((void**)&gV, g_Vh);
    cudaGetSymbolAddress((void**)&gY, g_Yh);
    cudaGetSymbolAddress((void**)&gX, g_Xh);
    cudaGetSymbolAddress((void**)&gM, g_Mh);
    cudaGetSymbolAddress((void**)&wq, g_Wqh);
    cudaGetSymbolAddress((void**)&wk, g_Wkh);
    cudaGetSymbolAddress((void**)&wv, g_Wvh);
    cudaGetSymbolAddress((void**)&wo, g_Woh);

    cudaFuncSetAttribute(gemm_fp16_kernel, cudaFuncAttributeMaxDynamicSharedMemorySize,
                         GEMM_SMEM_BYTES);
    cudaFuncSetAttribute(attn_kernel, cudaFuncAttributeMaxDynamicSharedMemorySize,
                         ATT_SMEM_BYTES);

    const int nact = BT * DM;    // 4M
    const int nw = DM * DM;      // 1M

    // 0,1: convert all GEMM operands to fp16
    convert3_kernel<<<1184, 256>>>(tgt, gX, nact, W_q, wq, nw, W_k, wk, nw);
    convert3_kernel<<<1184, 256>>>(memory, gM, nact, W_v, wv, nw, W_o, wo, nw);

    dim3 ggrid(DM / 128, BT / 128);   // (8, 32)
    // 2,3,4: projections, half outputs with fused bias
    gemm_fp16_kernel<<<ggrid, 256, GEMM_SMEM_BYTES>>>(gX, wq, b_q, gQ, DM, DM, 1);
    gemm_fp16_kernel<<<ggrid, 256, GEMM_SMEM_BYTES>>>(gM, wk, b_k, gK, DM, DM, 1);
    gemm_fp16_kernel<<<ggrid, 256, GEMM_SMEM_BYTES>>>(gM, wv, b_v, gV, DM, DM, 1);
    // 5: attention
    attn_kernel<<<dim3(TDEC / 64, NB * NHEADS), 256, ATT_SMEM_BYTES>>>(gQ, gK, gV, gY);
    // 6: output projection, float output
    gemm_fp16_kernel<<<ggrid, 256, GEMM_SMEM_BYTES>>>(gY, wo, b_o, out, DM, DM, 0);
}

// round 14
// speedup vs baseline: 3.3834x; 1.1144x over previous
#include <cuda_runtime.h>
#include <cuda_fp16.h>
#include <mma.h>
#include <cstdint>
using namespace nvcuda;

// Problem constants (fixed by the reference)
#define BT      4096      // B * T_dec = B * T_enc = 2 * 2048
#define DM      1024      // d_model
#define NHEADS  16
#define DH      64
#define TDEC    2048
#define TENC    2048
#define NB      2

// Scratch (allocation-free)
__device__ __half g_Qh[BT * DM];
__device__ __half g_Kh[BT * DM];
__device__ __half g_Vh[BT * DM];
__device__ __half g_Yh[BT * DM];
__device__ __half g_Xh[BT * DM];    // tgt, fp16
__device__ __half g_Mh[BT * DM];    // memory, fp16
__device__ __half g_Wqh[DM * DM];
__device__ __half g_Wkh[DM * DM];
__device__ __half g_Wvh[DM * DM];
__device__ __half g_Woh[DM * DM];

// ---------------------------------------------------------------------------
// helpers
// ---------------------------------------------------------------------------
__device__ __forceinline__ void cp_async16(void* smem_dst, const void* gmem_src) {
    unsigned sa = (unsigned)__cvta_generic_to_shared(smem_dst);
    asm volatile("cp.async.cg.shared.global [%0], [%1], 16;\n" :: "r"(sa), "l"(gmem_src));
}
__device__ __forceinline__ void cp_commit() {
    asm volatile("cp.async.commit_group;\n");
}
__device__ __forceinline__ void cp_wait_all() {
    asm volatile("cp.async.wait_group 0;\n");
}
__device__ __forceinline__ uint32_t smem_addr_u32(const void* p) {
    return (uint32_t)__cvta_generic_to_shared(p);
}
// PTX mma m16n8k16 fp16->fp32 (layouts verified in R13 run)
__device__ __forceinline__ void mma16n8k16(float* c, const uint32_t* a, const uint32_t* b) {
    asm volatile(
        "mma.sync.aligned.m16n8k16.row.col.f32.f16.f16.f32 "
        "{%0,%1,%2,%3}, {%4,%5,%6,%7}, {%8,%9}, {%0,%1,%2,%3};\n"
        : "+f"(c[0]), "+f"(c[1]), "+f"(c[2]), "+f"(c[3])
        : "r"(a[0]), "r"(a[1]), "r"(a[2]), "r"(a[3]), "r"(b[0]), "r"(b[1]));
}
__device__ __forceinline__ void ldmatrix_x4(uint32_t& r0, uint32_t& r1,
                                            uint32_t& r2, uint32_t& r3, uint32_t addr) {
    asm volatile("ldmatrix.sync.aligned.m8n8.x4.shared.b16 {%0,%1,%2,%3}, [%4];"
                 : "=r"(r0), "=r"(r1), "=r"(r2), "=r"(r3) : "r"(addr));
}
__device__ __forceinline__ void ldmatrix_x4_trans(uint32_t& r0, uint32_t& r1,
                                                  uint32_t& r2, uint32_t& r3, uint32_t addr) {
    asm volatile("ldmatrix.sync.aligned.m8n8.x4.trans.shared.b16 {%0,%1,%2,%3}, [%4];"
                 : "=r"(r0), "=r"(r1), "=r"(r2), "=r"(r3) : "r"(addr));
}
#define BAR_PAIR(id) asm volatile("bar.sync %0, 64;" :: "r"((id)) : "memory")

// ---------------------------------------------------------------------------
// Fused fp32 -> fp16 conversion of three tensors (grid-stride, float4 in)
// ---------------------------------------------------------------------------
__global__ void convert3_kernel(const float* __restrict__ s1, __half* __restrict__ d1, int n1,
                                const float* __restrict__ s2, __half* __restrict__ d2, int n2,
                                const float* __restrict__ s3, __half* __restrict__ d3, int n3)
{
    const int total4 = (n1 + n2 + n3) >> 2;
    for (int i = blockIdx.x * blockDim.x + threadIdx.x; i < total4;
         i += gridDim.x * blockDim.x) {
        int idx = i << 2;
        const float* s; __half* d;
        if (idx < n1)            { s = s1 + idx; d = d1 + idx; }
        else if (idx < n1 + n2)  { s = s2 + (idx - n1); d = d2 + (idx - n1); }
        else                     { s = s3 + (idx - n1 - n2); d = d3 + (idx - n1 - n2); }
        float4 v = *reinterpret_cast<const float4*>(s);
        __half2 h0 = __floats2half2_rn(v.x, v.y);
        __half2 h1 = __floats2half2_rn(v.z, v.w);
        uint2 u;
        u.x = *reinterpret_cast<uint32_t*>(&h0);
        u.y = *reinterpret_cast<uint32_t*>(&h1);
        *reinterpret_cast<uint2*>(d) = u;
    }
}

// ---------------------------------------------------------------------------
// FP16 tiled GEMM, double-buffered cp.async, BK=64, fused bias epilogue.
// C = X @ W (X: MxK row-major halves, W: KxN row-major halves).
// Tile 128x128, 8 warps (warp tile 32x64). Output: half (out_half) or float.
// ---------------------------------------------------------------------------
#define GLDA 72     // 64 + 8 pad (halves)
#define GLDB 136    // 128 + 8 pad (halves)
#define GLDC 132    // 128 + 4 pad (floats)
#define A_STG (128 * GLDA)              // 9216 halves per A stage
#define B_STG (64 * GLDB)               // 8704 halves per B stage
#define GEMM_SMEM_BYTES ((2 * A_STG + 2 * B_STG) * 2)   // 71680 >= Cs 67584

__global__ __launch_bounds__(256, 2) void gemm_fp16_kernel(
    const __half* __restrict__ X, const __half* __restrict__ W,
    const float* __restrict__ bias, void* __restrict__ Cout,
    int K, int N, int out_half)
{
    extern __shared__ char smraw[];
    __half* As = reinterpret_cast<__half*>(smraw);                     // [2][A_STG]
    __half* Bs = reinterpret_cast<__half*>(smraw + 2 * A_STG * 2);     // [2][B_STG]
    float*  Cs = reinterpret_cast<float*>(smraw);                      // epilogue alias

    const int bm = blockIdx.y * 128;
    const int bn = blockIdx.x * 128;
    const int tid = threadIdx.x;
    const int warp = tid >> 5;
    const int wm = warp >> 1;   // 0..3 -> row block of 32
    const int wn = warp & 1;    // 0..1 -> col block of 64

    wmma::fragment<wmma::accumulator, 16, 16, 16, float> acc[2][4];
    #pragma unroll
    for (int i = 0; i < 2; i++)
        #pragma unroll
        for (int j = 0; j < 4; j++)
            wmma::fill_fragment(acc[i][j], 0.0f);

    // stage loader: A 128x64h (1024 x 16B), B 64x128h (1024 x 16B); 4+4/thread
    auto load_stage = [&](int s, int k0) {
        #pragma unroll
        for (int i = tid; i < 1024; i += 256) {
            int row = i >> 3, c16 = i & 7;
            cp_async16(&As[s * A_STG + row * GLDA + c16 * 8],
                       &X[(size_t)(bm + row) * K + k0 + c16 * 8]);
        }
        #pragma unroll
        for (int i = tid; i < 1024; i += 256) {
            int row = i >> 4, c16 = i & 15;
            cp_async16(&Bs[s * B_STG + row * GLDB + c16 * 8],
                       &W[(size_t)(k0 + row) * N + bn + c16 * 8]);
        }
        cp_commit();
    };

    const int nk = K / 64;
    load_stage(0, 0);

    for (int kt = 0; kt < nk; kt++) {
        cp_wait_all();
        __syncthreads();
        if (kt + 1 < nk) load_stage((kt + 1) & 1, (kt + 1) * 64);
        const int s = kt & 1;

        #pragma unroll
        for (int kk = 0; kk < 64; kk += 16) {
            wmma::fragment<wmma::matrix_a, 16, 16, 16, __half, wmma::row_major> afr[2];
            wmma::fragment<wmma::matrix_b, 16, 16, 16, __half, wmma::row_major> bfr[4];
            #pragma unroll
            for (int mt = 0; mt < 2; mt++)
                wmma::load_matrix_sync(afr[mt],
                    &As[s * A_STG + (wm * 32 + mt * 16) * GLDA + kk], GLDA);
            #pragma unroll
            for (int nt = 0; nt < 4; nt++)
                wmma::load_matrix_sync(bfr[nt],
                    &Bs[s * B_STG + kk * GLDB + wn * 64 + nt * 16], GLDB);
            #pragma unroll
            for (int mt = 0; mt < 2; mt++)
                #pragma unroll
                for (int nt = 0; nt < 4; nt++)
                    wmma::mma_sync(acc[mt][nt], afr[mt], bfr[nt], acc[mt][nt]);
        }
    }

    // Epilogue: fragments -> smem (float), then bias -> global (half or float)
    __syncthreads();
    #pragma unroll
    for (int mt = 0; mt < 2; mt++)
        #pragma unroll
        for (int nt = 0; nt < 4; nt++)
            wmma::store_matrix_sync(
                &Cs[(size_t)(wm * 32 + mt * 16) * GLDC + wn * 64 + nt * 16],
                acc[mt][nt], GLDC, wmma::mem_row_major);
    __syncthreads();

    {
        const int row = tid >> 1;          // 2 threads per row
        const int half_ = tid & 1;         // 64 cols each
        const float* src = &Cs[(size_t)row * GLDC + half_ * 64];
        const float* bsrc = &bias[bn + half_ * 64];
        if (out_half) {
            __half* dst = (__half*)Cout + (size_t)(bm + row) * N + bn + half_ * 64;
            #pragma unroll
            for (int j = 0; j < 64; j += 8) {
                uint4 u;
                __half2 h0 = __floats2half2_rn(src[j + 0] + bsrc[j + 0], src[j + 1] + bsrc[j + 1]);
                __half2 h1 = __floats2half2_rn(src[j + 2] + bsrc[j + 2], src[j + 3] + bsrc[j + 3]);
                __half2 h2 = __floats2half2_rn(src[j + 4] + bsrc[j + 4], src[j + 5] + bsrc[j + 5]);
                __half2 h3 = __floats2half2_rn(src[j + 6] + bsrc[j + 6], src[j + 7] + bsrc[j + 7]);
                u.x = *reinterpret_cast<uint32_t*>(&h0);
                u.y = *reinterpret_cast<uint32_t*>(&h1);
                u.z = *reinterpret_cast<uint32_t*>(&h2);
                u.w = *reinterpret_cast<uint32_t*>(&h3);
                *reinterpret_cast<uint4*>(&dst[j]) = u;
            }
        } else {
            float* dst = (float*)Cout + (size_t)(bm + row) * N + bn + half_ * 64;
            #pragma unroll
            for (int j = 0; j < 64; j += 4) {
                float4 v;
                v.x = src[j + 0] + bsrc[j + 0];
                v.y = src[j + 1] + bsrc[j + 1];
                v.z = src[j + 2] + bsrc[j + 2];
                v.w = src[j + 3] + bsrc[j + 3];
                *reinterpret_cast<float4*>(&dst[j]) = v;
            }
        }
    }
}

// ---------------------------------------------------------------------------
// Flash attention (fp16): wmma S -> smem, pair-local softmax, ldmatrix PV.
// Warp pair wm = warps {2wm, 2wm+1} owns row stripe [16wm, 16wm+16): the
// S-write, softmax, P-write and PV-read for that stripe stay inside the pair,
// so only named 64-thread barriers are needed around softmax.
// One block = one (b,h) x 64 query rows, KC=64, double-buffered K/V.
// grid = (TDEC/64, B*NHEADS), 256 threads, 2 CTAs/SM.
// ---------------------------------------------------------------------------
#define KC      64
#define QLDH    72    // halves (Qs/Ps/Ks/Vs pad)
#define SLDF    68    // floats (Ss pad)
#define ATT_SS_OFF   0
#define ATT_QS_OFF   (64 * SLDF * 4)                       // 17408
#define ATT_PS_OFF   (ATT_QS_OFF + 64 * QLDH * 2)          // 26624
#define ATT_KS_OFF   (ATT_PS_OFF + 64 * QLDH * 2)          // 35840
#define ATT_VS_OFF   (ATT_KS_OFF + 2 * KC * QLDH * 2)      // 54272
#define ATT_ST_OFF   (ATT_VS_OFF + 2 * KC * QLDH * 2)      // 72704
#define ATT_SMEM_BYTES (ATT_ST_OFF + 192 * 4)              // 73472
#define NJT     (TENC / KC)      // 32

__global__ __launch_bounds__(256, 2) void attn_kernel(
    const __half* __restrict__ Q, const __half* __restrict__ K,
    const __half* __restrict__ V, __half* __restrict__ Y)
{
    extern __shared__ char smraw[];
    float*  Ss  = reinterpret_cast<float*>(smraw + ATT_SS_OFF);   // 64 x SLDF
    __half* Qs  = reinterpret_cast<__half*>(smraw + ATT_QS_OFF);  // 64 x QLDH
    __half* Ps  = reinterpret_cast<__half*>(smraw + ATT_PS_OFF);  // 64 x QLDH
    __half* Ks0 = reinterpret_cast<__half*>(smraw + ATT_KS_OFF);  // [2][KC x QLDH]
    __half* Vs0 = reinterpret_cast<__half*>(smraw + ATT_VS_OFF);  // [2][KC x QLDH]
    float*  m_s = reinterpret_cast<float*>(smraw + ATT_ST_OFF);   // 64
    float*  l_s = m_s + 64;                                       // 64
    float*  a_s = l_s + 64;                                       // 64

    const int bh = blockIdx.y;
    const int b  = bh >> 4;
    const int h  = bh & 15;
    const int q0 = blockIdx.x * 64;
    const int tid = threadIdx.x;
    const int warp = tid >> 5;
    const int lane = tid & 31;
    const int g   = lane >> 2;
    const int tg  = lane & 3;
    const int wm = warp >> 1;           // 0..3 -> 16-row stripe (pair id)
    const int wn = warp & 1;            // 0..1 -> 32-col half
    const int R0 = wm * 16;
    const int C0 = wn * 32;

    const uint32_t ps_base = smem_addr_u32(Ps);
    const uint32_t vs_base = smem_addr_u32(Vs0);

    auto prefetch_kv = [&](int s, int jt) {
        __half* Ksb = Ks0 + s * KC * QLDH;
        __half* Vsb = Vs0 + s * KC * QLDH;
        const int j0 = jt * KC;
        #pragma unroll
        for (int i = tid; i < 1024; i += 256) {
            if (i < 512) {
                int row = i >> 3, c16 = i & 7;
                cp_async16(&Ksb[row * QLDH + c16 * 8],
                           &K[(size_t)(b * TENC + j0 + row) * DM + h * DH + c16 * 8]);
            } else {
                int j = i - 512;
                int row = j >> 3, c16 = j & 7;
                cp_async16(&Vsb[row * QLDH + c16 * 8],
                           &V[(size_t)(b * TENC + j0 + row) * DM + h * DH + c16 * 8]);
            }
        }
        cp_commit();
    };

    // Load Q tile (64x64 halves), pre-scaled by 0.125 (exact in fp16)
    {
        const __half2 sc2 = __float2half2_rn(0.125f);
        __half2* Qs2 = reinterpret_cast<__half2*>(Qs);
        const __half2* Qg = reinterpret_cast<const __half2*>(Q);
        #pragma unroll
        for (int i = tid; i < 2048; i += 256) {
            int r = i >> 5, c2 = i & 31;
            __half2 v = Qg[(size_t)(b * TDEC + q0 + r) * (DM / 2) + h * 32 + c2];
            Qs2[r * (QLDH / 2) + c2] = __hmul2(v, sc2);
        }
    }
    if (tid < 64) { m_s[tid] = -1e30f; l_s[tid] = 0.0f; }

    // Register O accumulator: 4 n8-tiles x 4 f32 = 16x32 warp tile
    float o[4][4];
    #pragma unroll
    for (int nt = 0; nt < 4; nt++)
        #pragma unroll
        for (int e = 0; e < 4; e++) o[nt][e] = 0.0f;

    prefetch_kv(0, 0);

    for (int jt = 0; jt < NJT; jt++) {
        cp_wait_all();
        __syncthreads();                 // stage ready + all stage/smem reuse safe
        if (jt + 1 < NJT) prefetch_kv((jt + 1) & 1, jt + 1);
        const int st = jt & 1;
        const __half* Ksb = Ks0 + st * KC * QLDH;

        // ---- S = Qs @ Ks^T : 64 x 64, warp tile 16 x 32 (wmma fp16) ----
        {
            wmma::fragment<wmma::accumulator, 16, 16, 16, float> sacc[2];
            wmma::fill_fragment(sacc[0], 0.0f);
            wmma::fill_fragment(sacc[1], 0.0f);
            #pragma unroll
            for (int kk = 0; kk < 64; kk += 16) {
                wmma::fragment<wmma::matrix_a, 16, 16, 16, __half, wmma::row_major> afr;
                wmma::load_matrix_sync(afr, &Qs[R0 * QLDH + kk], QLDH);
                #pragma unroll
                for (int nt = 0; nt < 2; nt++) {
                    wmma::fragment<wmma::matrix_b, 16, 16, 16, __half, wmma::col_major> bfr;
                    wmma::load_matrix_sync(bfr, &Ksb[(C0 + nt * 16) * QLDH + kk], QLDH);
                    wmma::mma_sync(sacc[nt], afr, bfr, sacc[nt]);
                }
            }
            #pragma unroll
            for (int nt = 0; nt < 2; nt++)
                wmma::store_matrix_sync(&Ss[R0 * SLDF + C0 + nt * 16],
                                        sacc[nt], SLDF, wmma::mem_row_major);
        }
        BAR_PAIR(wm + 1);     // S stripe complete within pair

        // ---- online softmax: pair-local (rows 16wm..16wm+16), 4 thr/row ----
        {
            int r = tid >> 2, seg = tid & 3;
            float* Sr = &Ss[r * SLDF];
            __half* Pr = &Ps[r * QLDH];
            float mx = -1e30f;
            #pragma unroll
            for (int c = 0; c < 16; c++) mx = fmaxf(mx, Sr[seg + 4 * c]);
            mx = fmaxf(mx, __shfl_xor_sync(0xffffffffu, mx, 1));
            mx = fmaxf(mx, __shfl_xor_sync(0xffffffffu, mx, 2));
            float mold = m_s[r];
            float mnew = fmaxf(mold, mx);
            float alpha = __expf(mold - mnew);
            float sum = 0.0f;
            #pragma unroll
            for (int c = 0; c < 16; c++) {
                float p = __expf(Sr[seg + 4 * c] - mnew);
                sum += p;
                Pr[seg + 4 * c] = __float2half_rn(p);
            }
            sum += __shfl_xor_sync(0xffffffffu, sum, 1);
            sum += __shfl_xor_sync(0xffffffffu, sum, 2);
            if (seg == 0) {
                m_s[r] = mnew;
                l_s[r] = l_s[r] * alpha + sum;
                a_s[r] = alpha;
            }
        }
        BAR_PAIR(wm + 1);     // P stripe + alpha visible to pair

        // ---- O = O*alpha + P @ V : ldmatrix + PTX mma, O in registers ----
        {
            const float alo = a_s[R0 + g];
            const float ahi = a_s[R0 + 8 + g];
            #pragma unroll
            for (int nt = 0; nt < 4; nt++) {
                o[nt][0] *= alo; o[nt][1] *= alo;
                o[nt][2] *= ahi; o[nt][3] *= ahi;
            }
            const int lrow = lane & 15;
            const int lcol = (lane >> 4) * 8;
            const uint32_t pa0 = ps_base + 2u * ((R0 + lrow) * QLDH + lcol);
            const uint32_t va0 = vs_base + (uint32_t)(st * KC * QLDH * 2)
                               + 2u * (lrow * QLDH + C0 + lcol);
            #pragma unroll
            for (int k0 = 0; k0 < KC; k0 += 16) {
                uint32_t a[4];
                ldmatrix_x4(a[0], a[1], a[2], a[3], pa0 + 2u * k0);
                #pragma unroll
                for (int ntp = 0; ntp < 2; ntp++) {
                    uint32_t b0, b1, b2, b3;
                    ldmatrix_x4_trans(b0, b1, b2, b3,
                                      va0 + 2u * (k0 * QLDH + ntp * 16));
                    uint32_t bb0[2] = {b0, b1};
                    uint32_t bb1[2] = {b2, b3};
                    mma16n8k16(o[2 * ntp + 0], a, bb0);
                    mma16n8k16(o[2 * ntp + 1], a, bb1);
                }
            }
        }
        // next iteration's full sync protects Ss/Ps/stage reuse
    }
    __syncthreads();

    // Epilogue: Y (half) rows R0+g / R0+8+g, cols C0+8nt+2tg{,+1}
    {
        const float inv_lo = 1.0f / l_s[R0 + g];
        const float inv_hi = 1.0f / l_s[R0 + 8 + g];
        const size_t row_lo = (size_t)(b * TDEC + q0 + R0 + g) * DM + h * DH;
        const size_t row_hi = row_lo + (size_t)8 * DM;
        #pragma unroll
        for (int nt = 0; nt < 4; nt++) {
            const int c = C0 + nt * 8 + 2 * tg;
            __half2 vlo = __floats2half2_rn(o[nt][0] * inv_lo, o[nt][1] * inv_lo);
            __half2 vhi = __floats2half2_rn(o[nt][2] * inv_hi, o[nt][3] * inv_hi);
            *reinterpret_cast<__half2*>(&Y[row_lo + c]) = vlo;
            *reinterpret_cast<__half2*>(&Y[row_hi + c]) = vhi;
        }
    }
}

// ---------------------------------------------------------------------------
// Launcher.  Launch index 5 = attn_kernel (ncu -s 5 -c 1 profiles it).
// ---------------------------------------------------------------------------
extern "C" void kernel_launch(void* const* d_in, const int* in_sizes, int n_in,
                              void* d_out, int out_size)
{
    const float* tgt    = (const float*)d_in[0];
    const float* memory = (const float*)d_in[1];
    const float* W_q    = (const float*)d_in[2];
    const float* b_q    = (const float*)d_in[3];
    const float* W_k    = (const float*)d_in[4];
    const float* b_k    = (const float*)d_in[5];
    const float* W_v    = (const float*)d_in[6];
    const float* b_v    = (const float*)d_in[7];
    const float* W_o    = (const float*)d_in[8];
    const float* b_o    = (const float*)d_in[9];
    float* out = (float*)d_out;

    __half *gQ, *gK, *gV, *gY, *gX, *gM, *wq, *wk, *wv, *wo;
    cudaGetSymbolAddress((void**)&gQ, g_Qh);
    cudaGetSymbolAddress((void**)&gK, g_Kh);
    cudaGetSymbolAddress((void**)&gV, g_Vh);
    cudaGetSymbolAddress((void**)&gY, g_Yh);
    cudaGetSymbolAddress((void**)&gX, g_Xh);
    cudaGetSymbolAddress((void**)&gM, g_Mh);
    cudaGetSymbolAddress((void**)&wq, g_Wqh);
    cudaGetSymbolAddress((void**)&wk, g_Wkh);
    cudaGetSymbolAddress((void**)&wv, g_Wvh);
    cudaGetSymbolAddress((void**)&wo, g_Woh);

    cudaFuncSetAttribute(gemm_fp16_kernel, cudaFuncAttributeMaxDynamicSharedMemorySize,
                         GEMM_SMEM_BYTES);
    cudaFuncSetAttribute(attn_kernel, cudaFuncAttributeMaxDynamicSharedMemorySize,
                         ATT_SMEM_BYTES);

    const int nact = BT * DM;    // 4M
    const int nw = DM * DM;      // 1M

    // 0,1: convert all GEMM operands to fp16
    convert3_kernel<<<1184, 256>>>(tgt, gX, nact, W_q, wq, nw, W_k, wk, nw);
    convert3_kernel<<<1184, 256>>>(memory, gM, nact, W_v, wv, nw, W_o, wo, nw);

    dim3 ggrid(DM / 128, BT / 128);   // (8, 32)
    // 2,3,4: projections, half outputs with fused bias
    gemm_fp16_kernel<<<ggrid, 256, GEMM_SMEM_BYTES>>>(gX, wq, b_q, gQ, DM, DM, 1);
    gemm_fp16_kernel<<<ggrid, 256, GEMM_SMEM_BYTES>>>(gM, wk, b_k, gK, DM, DM, 1);
    gemm_fp16_kernel<<<ggrid, 256, GEMM_SMEM_BYTES>>>(gM, wv, b_v, gV, DM, DM, 1);
    // 5: attention (profiled launch)
    attn_kernel<<<dim3(TDEC / 64, NB * NHEADS), 256, ATT_SMEM_BYTES>>>(gQ, gK, gV, gY);
    // 6: output projection, float output
    gemm_fp16_kernel<<<ggrid, 256, GEMM_SMEM_BYTES>>>(gY, wo, b_o, out, DM, DM, 0);
}

// round 15
// speedup vs baseline: 3.9704x; 1.1735x over previous
#include <cuda_runtime.h>
#include <cuda_fp16.h>
#include <mma.h>
#include <cstdint>
using namespace nvcuda;

// Problem constants (fixed by the reference)
#define BT      4096      // B * T_dec = B * T_enc = 2 * 2048
#define DM      1024      // d_model
#define NHEADS  16
#define DH      64
#define TDEC    2048
#define TENC    2048
#define NB      2

// Scratch (allocation-free)
__device__ __half g_Qh[BT * DM];
__device__ __half g_Kh[BT * DM];
__device__ __half g_Vh[BT * DM];
__device__ __half g_Yh[BT * DM];
__device__ __half g_Xh[BT * DM];    // tgt, fp16
__device__ __half g_Mh[BT * DM];    // memory, fp16
__device__ __half g_Wqh[DM * DM];
__device__ __half g_Wkh[DM * DM];
__device__ __half g_Wvh[DM * DM];
__device__ __half g_Woh[DM * DM];

// ---------------------------------------------------------------------------
// helpers
// ---------------------------------------------------------------------------
__device__ __forceinline__ void cp_async16(void* smem_dst, const void* gmem_src) {
    unsigned sa = (unsigned)__cvta_generic_to_shared(smem_dst);
    asm volatile("cp.async.cg.shared.global [%0], [%1], 16;\n" :: "r"(sa), "l"(gmem_src));
}
__device__ __forceinline__ void cp_commit() {
    asm volatile("cp.async.commit_group;\n");
}
__device__ __forceinline__ void cp_wait_all() {
    asm volatile("cp.async.wait_group 0;\n");
}
__device__ __forceinline__ uint32_t smem_addr_u32(const void* p) {
    return (uint32_t)__cvta_generic_to_shared(p);
}
// PTX mma m16n8k16 fp16->fp32 (layouts verified R13/R14)
__device__ __forceinline__ void mma16n8k16(float* c, const uint32_t* a, const uint32_t* b) {
    asm volatile(
        "mma.sync.aligned.m16n8k16.row.col.f32.f16.f16.f32 "
        "{%0,%1,%2,%3}, {%4,%5,%6,%7}, {%8,%9}, {%0,%1,%2,%3};\n"
        : "+f"(c[0]), "+f"(c[1]), "+f"(c[2]), "+f"(c[3])
        : "r"(a[0]), "r"(a[1]), "r"(a[2]), "r"(a[3]), "r"(b[0]), "r"(b[1]));
}
__device__ __forceinline__ void ldmatrix_x4_trans(uint32_t& r0, uint32_t& r1,
                                                  uint32_t& r2, uint32_t& r3, uint32_t addr) {
    asm volatile("ldmatrix.sync.aligned.m8n8.x4.trans.shared.b16 {%0,%1,%2,%3}, [%4];"
                 : "=r"(r0), "=r"(r1), "=r"(r2), "=r"(r3) : "r"(addr));
}
__device__ __forceinline__ uint32_t pack_h2(float x, float y) {
    __half2 h = __floats2half2_rn(x, y);
    return *reinterpret_cast<uint32_t*>(&h);
}
#define BAR_PAIR(id) asm volatile("bar.sync %0, 64;" :: "r"((id)) : "memory")

// ---------------------------------------------------------------------------
// Fused fp32 -> fp16 conversion of three tensors (grid-stride, float4 in)
// ---------------------------------------------------------------------------
__global__ void convert3_kernel(const float* __restrict__ s1, __half* __restrict__ d1, int n1,
                                const float* __restrict__ s2, __half* __restrict__ d2, int n2,
                                const float* __restrict__ s3, __half* __restrict__ d3, int n3)
{
    const int total4 = (n1 + n2 + n3) >> 2;
    for (int i = blockIdx.x * blockDim.x + threadIdx.x; i < total4;
         i += gridDim.x * blockDim.x) {
        int idx = i << 2;
        const float* s; __half* d;
        if (idx < n1)            { s = s1 + idx; d = d1 + idx; }
        else if (idx < n1 + n2)  { s = s2 + (idx - n1); d = d2 + (idx - n1); }
        else                     { s = s3 + (idx - n1 - n2); d = d3 + (idx - n1 - n2); }
        float4 v = *reinterpret_cast<const float4*>(s);
        __half2 h0 = __floats2half2_rn(v.x, v.y);
        __half2 h1 = __floats2half2_rn(v.z, v.w);
        uint2 u;
        u.x = *reinterpret_cast<uint32_t*>(&h0);
        u.y = *reinterpret_cast<uint32_t*>(&h1);
        *reinterpret_cast<uint2*>(d) = u;
    }
}

// ---------------------------------------------------------------------------
// FP16 tiled GEMM, double-buffered cp.async, BK=64, fused bias epilogue.
// (unchanged from R14 passing version)
// ---------------------------------------------------------------------------
#define GLDA 72     // 64 + 8 pad (halves)
#define GLDB 136    // 128 + 8 pad (halves)
#define GLDC 132    // 128 + 4 pad (floats)
#define A_STG (128 * GLDA)              // 9216 halves per A stage
#define B_STG (64 * GLDB)               // 8704 halves per B stage
#define GEMM_SMEM_BYTES ((2 * A_STG + 2 * B_STG) * 2)   // 71680 >= Cs 67584

__global__ __launch_bounds__(256, 2) void gemm_fp16_kernel(
    const __half* __restrict__ X, const __half* __restrict__ W,
    const float* __restrict__ bias, void* __restrict__ Cout,
    int K, int N, int out_half)
{
    extern __shared__ char smraw[];
    __half* As = reinterpret_cast<__half*>(smraw);                     // [2][A_STG]
    __half* Bs = reinterpret_cast<__half*>(smraw + 2 * A_STG * 2);     // [2][B_STG]
    float*  Cs = reinterpret_cast<float*>(smraw);                      // epilogue alias

    const int bm = blockIdx.y * 128;
    const int bn = blockIdx.x * 128;
    const int tid = threadIdx.x;
    const int warp = tid >> 5;
    const int wm = warp >> 1;   // 0..3 -> row block of 32
    const int wn = warp & 1;    // 0..1 -> col block of 64

    wmma::fragment<wmma::accumulator, 16, 16, 16, float> acc[2][4];
    #pragma unroll
    for (int i = 0; i < 2; i++)
        #pragma unroll
        for (int j = 0; j < 4; j++)
            wmma::fill_fragment(acc[i][j], 0.0f);

    auto load_stage = [&](int s, int k0) {
        #pragma unroll
        for (int i = tid; i < 1024; i += 256) {
            int row = i >> 3, c16 = i & 7;
            cp_async16(&As[s * A_STG + row * GLDA + c16 * 8],
                       &X[(size_t)(bm + row) * K + k0 + c16 * 8]);
        }
        #pragma unroll
        for (int i = tid; i < 1024; i += 256) {
            int row = i >> 4, c16 = i & 15;
            cp_async16(&Bs[s * B_STG + row * GLDB + c16 * 8],
                       &W[(size_t)(k0 + row) * N + bn + c16 * 8]);
        }
        cp_commit();
    };

    const int nk = K / 64;
    load_stage(0, 0);

    for (int kt = 0; kt < nk; kt++) {
        cp_wait_all();
        __syncthreads();
        if (kt + 1 < nk) load_stage((kt + 1) & 1, (kt + 1) * 64);
        const int s = kt & 1;

        #pragma unroll
        for (int kk = 0; kk < 64; kk += 16) {
            wmma::fragment<wmma::matrix_a, 16, 16, 16, __half, wmma::row_major> afr[2];
            wmma::fragment<wmma::matrix_b, 16, 16, 16, __half, wmma::row_major> bfr[4];
            #pragma unroll
            for (int mt = 0; mt < 2; mt++)
                wmma::load_matrix_sync(afr[mt],
                    &As[s * A_STG + (wm * 32 + mt * 16) * GLDA + kk], GLDA);
            #pragma unroll
            for (int nt = 0; nt < 4; nt++)
                wmma::load_matrix_sync(bfr[nt],
                    &Bs[s * B_STG + kk * GLDB + wn * 64 + nt * 16], GLDB);
            #pragma unroll
            for (int mt = 0; mt < 2; mt++)
                #pragma unroll
                for (int nt = 0; nt < 4; nt++)
                    wmma::mma_sync(acc[mt][nt], afr[mt], bfr[nt], acc[mt][nt]);
        }
    }

    __syncthreads();
    #pragma unroll
    for (int mt = 0; mt < 2; mt++)
        #pragma unroll
        for (int nt = 0; nt < 4; nt++)
            wmma::store_matrix_sync(
                &Cs[(size_t)(wm * 32 + mt * 16) * GLDC + wn * 64 + nt * 16],
                acc[mt][nt], GLDC, wmma::mem_row_major);
    __syncthreads();

    {
        const int row = tid >> 1;
        const int half_ = tid & 1;
        const float* src = &Cs[(size_t)row * GLDC + half_ * 64];
        const float* bsrc = &bias[bn + half_ * 64];
        if (out_half) {
            __half* dst = (__half*)Cout + (size_t)(bm + row) * N + bn + half_ * 64;
            #pragma unroll
            for (int j = 0; j < 64; j += 8) {
                uint4 u;
                __half2 h0 = __floats2half2_rn(src[j + 0] + bsrc[j + 0], src[j + 1] + bsrc[j + 1]);
                __half2 h1 = __floats2half2_rn(src[j + 2] + bsrc[j + 2], src[j + 3] + bsrc[j + 3]);
                __half2 h2 = __floats2half2_rn(src[j + 4] + bsrc[j + 4], src[j + 5] + bsrc[j + 5]);
                __half2 h3 = __floats2half2_rn(src[j + 6] + bsrc[j + 6], src[j + 7] + bsrc[j + 7]);
                u.x = *reinterpret_cast<uint32_t*>(&h0);
                u.y = *reinterpret_cast<uint32_t*>(&h1);
                u.z = *reinterpret_cast<uint32_t*>(&h2);
                u.w = *reinterpret_cast<uint32_t*>(&h3);
                *reinterpret_cast<uint4*>(&dst[j]) = u;
            }
        } else {
            float* dst = (float*)Cout + (size_t)(bm + row) * N + bn + half_ * 64;
            #pragma unroll
            for (int j = 0; j < 64; j += 4) {
                float4 v;
                v.x = src[j + 0] + bsrc[j + 0];
                v.y = src[j + 1] + bsrc[j + 1];
                v.z = src[j + 2] + bsrc[j + 2];
                v.w = src[j + 3] + bsrc[j + 3];
                *reinterpret_cast<float4*>(&dst[j]) = v;
            }
        }
    }
}

// ---------------------------------------------------------------------------
// Flash attention v4 (fp16, all-register S/P/O, split-K pairs):
//  - Q A-fragments in registers (loaded once from global)
//  - S = Q K^T via raw mma; K B-frags = direct half2 LDS (conflict-free)
//  - warp pair splits the 64 keys: warp wn owns keys [32wn, 32wn+32)
//  - softmax: warp-local + tiny smem exchange of row max/sum (2 pair barriers)
//  - P = register repack of S accumulators (never touches smem)
//  - O partial (16x64) per warp over its keys; pair-summed once at the end
// One block = one (b,h) x 64 query rows, KC=64, double-buffered K/V.
// grid = (TDEC/64, B*NHEADS), 256 threads, smem 37.9 KB, 2 CTAs/SM.
// ---------------------------------------------------------------------------
#define KC      64
#define QLDH    72
#define ATT_KS_BYTES (2 * KC * QLDH * 2)      // 18432
#define ATT_VS_BYTES (2 * KC * QLDH * 2)      // 18432
#define ATT_EX_OFF   (ATT_KS_BYTES + ATT_VS_BYTES)     // 36864
#define ATT_SMEM_BYTES (ATT_EX_OFF + 256 * 4)          // 37888
#define OLD     68    // obuf float stride
#define NJT     (TENC / KC)      // 32

__global__ __launch_bounds__(256, 2) void attn_kernel(
    const __half* __restrict__ Q, const __half* __restrict__ K,
    const __half* __restrict__ V, __half* __restrict__ Y)
{
    extern __shared__ char smraw[];
    __half* Ks0 = reinterpret_cast<__half*>(smraw);                    // [2][KC x QLDH]
    __half* Vs0 = reinterpret_cast<__half*>(smraw + ATT_KS_BYTES);     // [2][KC x QLDH]
    float*  m_ex = reinterpret_cast<float*>(smraw + ATT_EX_OFF);       // [2][64]
    float*  l_ex = m_ex + 128;                                         // [2][64]
    float*  obuf = reinterpret_cast<float*>(smraw);                    // epilogue alias (Ks area)

    const int bh = blockIdx.y;
    const int b  = bh >> 4;
    const int h  = bh & 15;
    const int q0 = blockIdx.x * 64;
    const int tid = threadIdx.x;
    const int warp = tid >> 5;
    const int lane = tid & 31;
    const int g   = lane >> 2;          // 0..7
    const int tg  = lane & 3;           // 0..3
    const int wm = warp >> 1;           // pair id 0..3 -> 16-row stripe
    const int wn = warp & 1;            // 0..1 -> key half (split-K)
    const int R0 = wm * 16;
    const int C0 = wn * 32;             // this warp's key offset within chunk

    const uint32_t vs_base = smem_addr_u32(Vs0);

    auto prefetch_kv = [&](int s, int jt) {
        __half* Ksb = Ks0 + s * KC * QLDH;
        __half* Vsb = Vs0 + s * KC * QLDH;
        const int j0 = jt * KC;
        #pragma unroll
        for (int i = tid; i < 1024; i += 256) {
            if (i < 512) {
                int row = i >> 3, c16 = i & 7;
                cp_async16(&Ksb[row * QLDH + c16 * 8],
                           &K[(size_t)(b * TENC + j0 + row) * DM + h * DH + c16 * 8]);
            } else {
                int j = i - 512;
                int row = j >> 3, c16 = j & 7;
                cp_async16(&Vsb[row * QLDH + c16 * 8],
                           &V[(size_t)(b * TENC + j0 + row) * DM + h * DH + c16 * 8]);
            }
        }
        cp_commit();
    };

    // ---- Q A-fragments in registers (4 k16-tiles x 4 regs), scaled 0.125 ----
    uint32_t qa[4][4];
    {
        const __half2 sc2 = __float2half2_rn(0.125f);
        const __half* Qb = Q + (size_t)(b * TDEC + q0 + R0) * DM + h * DH;
        #pragma unroll
        for (int kt = 0; kt < 4; kt++) {
            __half2 v0 = *reinterpret_cast<const __half2*>(&Qb[(size_t)g * DM + 16 * kt + 2 * tg]);
            __half2 v1 = *reinterpret_cast<const __half2*>(&Qb[(size_t)(g + 8) * DM + 16 * kt + 2 * tg]);
            __half2 v2 = *reinterpret_cast<const __half2*>(&Qb[(size_t)g * DM + 16 * kt + 2 * tg + 8]);
            __half2 v3 = *reinterpret_cast<const __half2*>(&Qb[(size_t)(g + 8) * DM + 16 * kt + 2 * tg + 8]);
            v0 = __hmul2(v0, sc2); v1 = __hmul2(v1, sc2);
            v2 = __hmul2(v2, sc2); v3 = __hmul2(v3, sc2);
            qa[kt][0] = *reinterpret_cast<uint32_t*>(&v0);
            qa[kt][1] = *reinterpret_cast<uint32_t*>(&v1);
            qa[kt][2] = *reinterpret_cast<uint32_t*>(&v2);
            qa[kt][3] = *reinterpret_cast<uint32_t*>(&v3);
        }
    }

    // Partial O over this warp's keys: 16 rows x 64 dh cols = 8 n8-tiles
    float o[8][4];
    #pragma unroll
    for (int nt = 0; nt < 8; nt++)
        #pragma unroll
        for (int e = 0; e < 4; e++) o[nt][e] = 0.0f;
    float m0 = -1e30f, m1 = -1e30f, l0 = 0.0f, l1 = 0.0f;

    prefetch_kv(0, 0);

    for (int jt = 0; jt < NJT; jt++) {
        cp_wait_all();
        __syncthreads();
        if (jt + 1 < NJT) prefetch_kv((jt + 1) & 1, jt + 1);
        const int st = jt & 1;
        const __half* Ksb = Ks0 + st * KC * QLDH;
        const uint32_t vsst = vs_base + (uint32_t)(st * KC * QLDH * 2);

        // ---- S = Q K^T : 16 rows x 32 keys, in registers ----
        float s[4][4];
        #pragma unroll
        for (int j = 0; j < 4; j++)
            #pragma unroll
            for (int e = 0; e < 4; e++) s[j][e] = 0.0f;
        #pragma unroll
        for (int kt = 0; kt < 4; kt++) {
            #pragma unroll
            for (int j = 0; j < 4; j++) {
                uint32_t bb[2];
                const __half* Kr = &Ksb[(C0 + 8 * j + g) * QLDH + 16 * kt + 2 * tg];
                bb[0] = *reinterpret_cast<const uint32_t*>(&Kr[0]);
                bb[1] = *reinterpret_cast<const uint32_t*>(&Kr[8]);
                mma16n8k16(s[j], qa[kt], bb);
            }
        }

        // ---- split-K online softmax (rows R0+g, R0+8+g) ----
        {
            float px0 = -1e30f, px1 = -1e30f;
            #pragma unroll
            for (int j = 0; j < 4; j++) {
                px0 = fmaxf(px0, fmaxf(s[j][0], s[j][1]));
                px1 = fmaxf(px1, fmaxf(s[j][2], s[j][3]));
            }
            px0 = fmaxf(px0, __shfl_xor_sync(0xffffffffu, px0, 1));
            px0 = fmaxf(px0, __shfl_xor_sync(0xffffffffu, px0, 2));
            px1 = fmaxf(px1, __shfl_xor_sync(0xffffffffu, px1, 1));
            px1 = fmaxf(px1, __shfl_xor_sync(0xffffffffu, px1, 2));
            if (tg == 0) {
                m_ex[wn * 64 + R0 + g] = px0;
                m_ex[wn * 64 + R0 + 8 + g] = px1;
            }
            BAR_PAIR(wm + 1);
            const float mo0 = m_ex[(1 - wn) * 64 + R0 + g];
            const float mo1 = m_ex[(1 - wn) * 64 + R0 + 8 + g];
            const float m0n = fmaxf(m0, fmaxf(px0, mo0));
            const float m1n = fmaxf(m1, fmaxf(px1, mo1));
            const float al0 = __expf(m0 - m0n);
            const float al1 = __expf(m1 - m1n);
            float ps0 = 0.0f, ps1 = 0.0f;
            #pragma unroll
            for (int j = 0; j < 4; j++) {
                s[j][0] = __expf(s[j][0] - m0n);
                s[j][1] = __expf(s[j][1] - m0n);
                s[j][2] = __expf(s[j][2] - m1n);
                s[j][3] = __expf(s[j][3] - m1n);
                ps0 += s[j][0] + s[j][1];
                ps1 += s[j][2] + s[j][3];
            }
            ps0 += __shfl_xor_sync(0xffffffffu, ps0, 1);
            ps0 += __shfl_xor_sync(0xffffffffu, ps0, 2);
            ps1 += __shfl_xor_sync(0xffffffffu, ps1, 1);
            ps1 += __shfl_xor_sync(0xffffffffu, ps1, 2);
            if (tg == 0) {
                l_ex[wn * 64 + R0 + g] = ps0;
                l_ex[wn * 64 + R0 + 8 + g] = ps1;
            }
            BAR_PAIR(wm + 1);
            l0 = l0 * al0 + ps0 + l_ex[(1 - wn) * 64 + R0 + g];
            l1 = l1 * al1 + ps1 + l_ex[(1 - wn) * 64 + R0 + 8 + g];
            m0 = m0n; m1 = m1n;
            #pragma unroll
            for (int nt = 0; nt < 8; nt++) {
                o[nt][0] *= al0; o[nt][1] *= al0;
                o[nt][2] *= al1; o[nt][3] *= al1;
            }
        }

        // ---- O += P @ V over this warp's 32 keys; P = register repack ----
        {
            const int lrow = lane & 15;
            const int lcol = (lane >> 4) * 8;
            #pragma unroll
            for (int kt2 = 0; kt2 < 2; kt2++) {
                uint32_t a[4];
                a[0] = pack_h2(s[2 * kt2][0], s[2 * kt2][1]);
                a[1] = pack_h2(s[2 * kt2][2], s[2 * kt2][3]);
                a[2] = pack_h2(s[2 * kt2 + 1][0], s[2 * kt2 + 1][1]);
                a[3] = pack_h2(s[2 * kt2 + 1][2], s[2 * kt2 + 1][3]);
                const uint32_t va = vsst
                    + 2u * ((C0 + 16 * kt2 + lrow) * QLDH + lcol);
                #pragma unroll
                for (int n16 = 0; n16 < 4; n16++) {
                    uint32_t b0, b1, b2, b3;
                    ldmatrix_x4_trans(b0, b1, b2, b3, va + 2u * (16 * n16));
                    uint32_t bb0[2] = {b0, b1};
                    uint32_t bb1[2] = {b2, b3};
                    mma16n8k16(o[2 * n16 + 0], a, bb0);
                    mma16n8k16(o[2 * n16 + 1], a, bb1);
                }
            }
        }
    }
    __syncthreads();   // all K/V reads done; Ks area reusable as obuf

    // ---- pair-sum partial O, then write Y ----
    {
        float* ob = obuf + wm * 16 * OLD;
        if (wn == 0) {
            #pragma unroll
            for (int nt = 0; nt < 8; nt++) {
                ob[g * OLD + 8 * nt + 2 * tg]       = o[nt][0];
                ob[g * OLD + 8 * nt + 2 * tg + 1]   = o[nt][1];
                ob[(g + 8) * OLD + 8 * nt + 2 * tg]     = o[nt][2];
                ob[(g + 8) * OLD + 8 * nt + 2 * tg + 1] = o[nt][3];
            }
        }
        BAR_PAIR(wm + 1);
        if (wn == 1) {
            const float inv0 = 1.0f / l0;
            const float inv1 = 1.0f / l1;
            const size_t row_lo = (size_t)(b * TDEC + q0 + R0 + g) * DM + h * DH;
            const size_t row_hi = row_lo + (size_t)8 * DM;
            #pragma unroll
            for (int nt = 0; nt < 8; nt++) {
                const int c = 8 * nt + 2 * tg;
                float x0 = (o[nt][0] + ob[g * OLD + c]) * inv0;
                float x1 = (o[nt][1] + ob[g * OLD + c + 1]) * inv0;
                float x2 = (o[nt][2] + ob[(g + 8) * OLD + c]) * inv1;
                float x3 = (o[nt][3] + ob[(g + 8) * OLD + c + 1]) * inv1;
                __half2 vlo = __floats2half2_rn(x0, x1);
                __half2 vhi = __floats2half2_rn(x2, x3);
                *reinterpret_cast<__half2*>(&Y[row_lo + c]) = vlo;
                *reinterpret_cast<__half2*>(&Y[row_hi + c]) = vhi;
            }
        }
    }
}

// ---------------------------------------------------------------------------
// Launcher.  Launch index 5 = attn_kernel (ncu -s 5 -c 1 profiles it).
// ---------------------------------------------------------------------------
extern "C" void kernel_launch(void* const* d_in, const int* in_sizes, int n_in,
                              void* d_out, int out_size)
{
    const float* tgt    = (const float*)d_in[0];
    const float* memory = (const float*)d_in[1];
    const float* W_q    = (const float*)d_in[2];
    const float* b_q    = (const float*)d_in[3];
    const float* W_k    = (const float*)d_in[4];
    const float* b_k    = (const float*)d_in[5];
    const float* W_v    = (const float*)d_in[6];
    const float* b_v    = (const float*)d_in[7];
    const float* W_o    = (const float*)d_in[8];
    const float* b_o    = (const float*)d_in[9];
    float* out = (float*)d_out;

    __half *gQ, *gK, *gV, *gY, *gX, *gM, *wq, *wk, *wv, *wo;
    cudaGetSymbolAddress((void**)&gQ, g_Qh);
    cudaGetSymbolAddress((void**)&gK, g_Kh);
    cudaGetSymbolAddress((void**)&gV, g_Vh);
    cudaGetSymbolAddress((void**)&gY, g_Yh);
    cudaGetSymbolAddress((void**)&gX, g_Xh);
    cudaGetSymbolAddress((void**)&gM, g_Mh);
    cudaGetSymbolAddress((void**)&wq, g_Wqh);
    cudaGetSymbolAddress((void**)&wk, g_Wkh);
    cudaGetSymbolAddress((void**)&wv, g_Wvh);
    cudaGetSymbolAddress((void**)&wo, g_Woh);

    cudaFuncSetAttribute(gemm_fp16_kernel, cudaFuncAttributeMaxDynamicSharedMemorySize,
                         GEMM_SMEM_BYTES);
    cudaFuncSetAttribute(attn_kernel, cudaFuncAttributeMaxDynamicSharedMemorySize,
                         ATT_SMEM_BYTES);

    const int nact = BT * DM;    // 4M
    const int nw = DM * DM;      // 1M

    // 0,1: convert all GEMM operands to fp16
    convert3_kernel<<<1184, 256>>>(tgt, gX, nact, W_q, wq, nw, W_k, wk, nw);
    convert3_kernel<<<1184, 256>>>(memory, gM, nact, W_v, wv, nw, W_o, wo, nw);

    dim3 ggrid(DM / 128, BT / 128);   // (8, 32)
    // 2,3,4: projections, half outputs with fused bias
    gemm_fp16_kernel<<<ggrid, 256, GEMM_SMEM_BYTES>>>(gX, wq, b_q, gQ, DM, DM, 1);
    gemm_fp16_kernel<<<ggrid, 256, GEMM_SMEM_BYTES>>>(gM, wk, b_k, gK, DM, DM, 1);
    gemm_fp16_kernel<<<ggrid, 256, GEMM_SMEM_BYTES>>>(gM, wv, b_v, gV, DM, DM, 1);
    // 5: attention (profiled launch)
    attn_kernel<<<dim3(TDEC / 64, NB * NHEADS), 256, ATT_SMEM_BYTES>>>(gQ, gK, gV, gY);
    // 6: output projection, float output
    gemm_fp16_kernel<<<ggrid, 256, GEMM_SMEM_BYTES>>>(gY, wo, b_o, out, DM, DM, 0);
}

// round 16
// speedup vs baseline: 4.1783x; 1.0524x over previous
#include <cuda_runtime.h>
#include <cuda_fp16.h>
#include <mma.h>
#include <cstdint>
using namespace nvcuda;

// Problem constants (fixed by the reference)
#define BT      4096      // B * T_dec = B * T_enc = 2 * 2048
#define DM      1024      // d_model
#define NHEADS  16
#define DH      64
#define TDEC    2048
#define TENC    2048
#define NB      2
#define KVSTR   2048      // fused KV buffer row stride (K cols 0-1023, V 1024-2047)

// Scratch (allocation-free)
__device__ __half g_Qh[BT * DM];
__device__ __half g_KVh[BT * KVSTR];   // fused K|V
__device__ __half g_Yh[BT * DM];
__device__ __half g_Xh[BT * DM];       // tgt, fp16
__device__ __half g_Mh[BT * DM];       // memory, fp16
__device__ __half g_Wqh[DM * DM];
__device__ __half g_WKVh[DM * KVSTR];  // fused W_k|W_v
__device__ __half g_Woh[DM * DM];
__device__ float  g_bkv[KVSTR];        // fused b_k|b_v

// ---------------------------------------------------------------------------
// helpers
// ---------------------------------------------------------------------------
__device__ __forceinline__ void cp_async16(void* smem_dst, const void* gmem_src) {
    unsigned sa = (unsigned)__cvta_generic_to_shared(smem_dst);
    asm volatile("cp.async.cg.shared.global [%0], [%1], 16;\n" :: "r"(sa), "l"(gmem_src));
}
__device__ __forceinline__ void cp_commit() {
    asm volatile("cp.async.commit_group;\n");
}
__device__ __forceinline__ void cp_wait_all() {
    asm volatile("cp.async.wait_group 0;\n");
}
__device__ __forceinline__ uint32_t smem_addr_u32(const void* p) {
    return (uint32_t)__cvta_generic_to_shared(p);
}
// PTX mma m16n8k16 fp16->fp32 (layouts verified R13-R15)
__device__ __forceinline__ void mma16n8k16(float* c, const uint32_t* a, const uint32_t* b) {
    asm volatile(
        "mma.sync.aligned.m16n8k16.row.col.f32.f16.f16.f32 "
        "{%0,%1,%2,%3}, {%4,%5,%6,%7}, {%8,%9}, {%0,%1,%2,%3};\n"
        : "+f"(c[0]), "+f"(c[1]), "+f"(c[2]), "+f"(c[3])
        : "r"(a[0]), "r"(a[1]), "r"(a[2]), "r"(a[3]), "r"(b[0]), "r"(b[1]));
}
__device__ __forceinline__ void ldmatrix_x4_trans(uint32_t& r0, uint32_t& r1,
                                                  uint32_t& r2, uint32_t& r3, uint32_t addr) {
    asm volatile("ldmatrix.sync.aligned.m8n8.x4.trans.shared.b16 {%0,%1,%2,%3}, [%4];"
                 : "=r"(r0), "=r"(r1), "=r"(r2), "=r"(r3) : "r"(addr));
}
__device__ __forceinline__ uint32_t pack_h2(float x, float y) {
    __half2 h = __floats2half2_rn(x, y);
    return *reinterpret_cast<uint32_t*>(&h);
}
#define BAR_PAIR(id) asm volatile("bar.sync %0, 64;" :: "r"((id)) : "memory")

// ---------------------------------------------------------------------------
// One-shot conversion: tgt, memory, W_q, W_k|W_v (concat), W_o  -> fp16,
// plus b_k|b_v concat (fp32).  Grid-stride over 12M floats.
// ---------------------------------------------------------------------------
__global__ void convert_all_kernel(
    const float* __restrict__ tgt, const float* __restrict__ mem,
    const float* __restrict__ Wq, const float* __restrict__ Wk,
    const float* __restrict__ Wv, const float* __restrict__ Wo,
    const float* __restrict__ bk, const float* __restrict__ bv)
{
    const int NA = BT * DM;     // 4M
    const int NW = DM * DM;     // 1M
    const int total4 = (2 * NA + 4 * NW) >> 2;
    for (int i = blockIdx.x * blockDim.x + threadIdx.x; i < total4;
         i += gridDim.x * blockDim.x) {
        int idx = i << 2;
        const float* s; __half* d;
        if (idx < NA)                    { s = tgt + idx; d = g_Xh + idx; }
        else if (idx < 2 * NA)           { s = mem + (idx - NA); d = g_Mh + (idx - NA); }
        else if (idx < 2 * NA + NW)      { s = Wq + (idx - 2 * NA); d = g_Wqh + (idx - 2 * NA); }
        else if (idx < 2 * NA + 2 * NW) {
            int l = idx - (2 * NA + NW);
            s = Wk + l;
            d = g_WKVh + ((l >> 10) << 11) + (l & 1023);          // K -> cols 0-1023
        } else if (idx < 2 * NA + 3 * NW) {
            int l = idx - (2 * NA + 2 * NW);
            s = Wv + l;
            d = g_WKVh + ((l >> 10) << 11) + (l & 1023) + 1024;   // V -> cols 1024-2047
        } else {
            int l = idx - (2 * NA + 3 * NW);
            s = Wo + l; d = g_Woh + l;
        }
        float4 v = *reinterpret_cast<const float4*>(s);
        __half2 h0 = __floats2half2_rn(v.x, v.y);
        __half2 h1 = __floats2half2_rn(v.z, v.w);
        uint2 u;
        u.x = *reinterpret_cast<uint32_t*>(&h0);
        u.y = *reinterpret_cast<uint32_t*>(&h1);
        *reinterpret_cast<uint2*>(d) = u;
    }
    if (blockIdx.x == 0 && threadIdx.x < 512) {
        int t = threadIdx.x * 4;
        float4 v = (t < 1024) ? *reinterpret_cast<const float4*>(bk + t)
                              : *reinterpret_cast<const float4*>(bv + (t - 1024));
        *reinterpret_cast<float4*>(g_bkv + t) = v;
    }
}

// ---------------------------------------------------------------------------
// Shared fp16 GEMM mainloop body (tile 128x128, BK=64, 8 warps, double-buffer)
// ---------------------------------------------------------------------------
#define GLDA 72     // 64 + 8 pad (halves)
#define GLDB 136    // 128 + 8 pad (halves)
#define GLDC 132    // 128 + 4 pad (floats)
#define A_STG (128 * GLDA)              // 9216 halves per A stage
#define B_STG (64 * GLDB)               // 8704 halves per B stage
#define GEMM_SMEM_BYTES ((2 * A_STG + 2 * B_STG) * 2)   // 71680 >= Cs 67584

__device__ __forceinline__ void gemm_body(
    const __half* __restrict__ X, const __half* __restrict__ W,
    const float* __restrict__ bias, void* __restrict__ Cout,
    int K, int N, int bm, int bn, int out_half, char* smraw)
{
    __half* As = reinterpret_cast<__half*>(smraw);
    __half* Bs = reinterpret_cast<__half*>(smraw + 2 * A_STG * 2);
    float*  Cs = reinterpret_cast<float*>(smraw);

    const int tid = threadIdx.x;
    const int warp = tid >> 5;
    const int wm = warp >> 1;
    const int wn = warp & 1;

    wmma::fragment<wmma::accumulator, 16, 16, 16, float> acc[2][4];
    #pragma unroll
    for (int i = 0; i < 2; i++)
        #pragma unroll
        for (int j = 0; j < 4; j++)
            wmma::fill_fragment(acc[i][j], 0.0f);

    auto load_stage = [&](int s, int k0) {
        #pragma unroll
        for (int i = tid; i < 1024; i += 256) {
            int row = i >> 3, c16 = i & 7;
            cp_async16(&As[s * A_STG + row * GLDA + c16 * 8],
                       &X[(size_t)(bm + row) * K + k0 + c16 * 8]);
        }
        #pragma unroll
        for (int i = tid; i < 1024; i += 256) {
            int row = i >> 4, c16 = i & 15;
            cp_async16(&Bs[s * B_STG + row * GLDB + c16 * 8],
                       &W[(size_t)(k0 + row) * N + bn + c16 * 8]);
        }
        cp_commit();
    };

    const int nk = K / 64;
    load_stage(0, 0);

    for (int kt = 0; kt < nk; kt++) {
        cp_wait_all();
        __syncthreads();
        if (kt + 1 < nk) load_stage((kt + 1) & 1, (kt + 1) * 64);
        const int s = kt & 1;

        #pragma unroll
        for (int kk = 0; kk < 64; kk += 16) {
            wmma::fragment<wmma::matrix_a, 16, 16, 16, __half, wmma::row_major> afr[2];
            wmma::fragment<wmma::matrix_b, 16, 16, 16, __half, wmma::row_major> bfr[4];
            #pragma unroll
            for (int mt = 0; mt < 2; mt++)
                wmma::load_matrix_sync(afr[mt],
                    &As[s * A_STG + (wm * 32 + mt * 16) * GLDA + kk], GLDA);
            #pragma unroll
            for (int nt = 0; nt < 4; nt++)
                wmma::load_matrix_sync(bfr[nt],
                    &Bs[s * B_STG + kk * GLDB + wn * 64 + nt * 16], GLDB);
            #pragma unroll
            for (int mt = 0; mt < 2; mt++)
                #pragma unroll
                for (int nt = 0; nt < 4; nt++)
                    wmma::mma_sync(acc[mt][nt], afr[mt], bfr[nt], acc[mt][nt]);
        }
    }

    __syncthreads();
    #pragma unroll
    for (int mt = 0; mt < 2; mt++)
        #pragma unroll
        for (int nt = 0; nt < 4; nt++)
            wmma::store_matrix_sync(
                &Cs[(size_t)(wm * 32 + mt * 16) * GLDC + wn * 64 + nt * 16],
                acc[mt][nt], GLDC, wmma::mem_row_major);
    __syncthreads();

    {
        const int row = tid >> 1;
        const int half_ = tid & 1;
        const float* src = &Cs[(size_t)row * GLDC + half_ * 64];
        const float* bsrc = &bias[bn + half_ * 64];
        if (out_half) {
            __half* dst = (__half*)Cout + (size_t)(bm + row) * N + bn + half_ * 64;
            #pragma unroll
            for (int j = 0; j < 64; j += 8) {
                uint4 u;
                __half2 h0 = __floats2half2_rn(src[j + 0] + bsrc[j + 0], src[j + 1] + bsrc[j + 1]);
                __half2 h1 = __floats2half2_rn(src[j + 2] + bsrc[j + 2], src[j + 3] + bsrc[j + 3]);
                __half2 h2 = __floats2half2_rn(src[j + 4] + bsrc[j + 4], src[j + 5] + bsrc[j + 5]);
                __half2 h3 = __floats2half2_rn(src[j + 6] + bsrc[j + 6], src[j + 7] + bsrc[j + 7]);
                u.x = *reinterpret_cast<uint32_t*>(&h0);
                u.y = *reinterpret_cast<uint32_t*>(&h1);
                u.z = *reinterpret_cast<uint32_t*>(&h2);
                u.w = *reinterpret_cast<uint32_t*>(&h3);
                *reinterpret_cast<uint4*>(&dst[j]) = u;
            }
        } else {
            float* dst = (float*)Cout + (size_t)(bm + row) * N + bn + half_ * 64;
            #pragma unroll
            for (int j = 0; j < 64; j += 4) {
                float4 v;
                v.x = src[j + 0] + bsrc[j + 0];
                v.y = src[j + 1] + bsrc[j + 1];
                v.z = src[j + 2] + bsrc[j + 2];
                v.w = src[j + 3] + bsrc[j + 3];
                *reinterpret_cast<float4*>(&dst[j]) = v;
            }
        }
    }
}

// Fused Q/K/V projection: grid.x = 8 (Q tiles) + 16 (KV tiles), grid.y = 32.
__global__ __launch_bounds__(256, 2) void proj3_kernel()
{
    extern __shared__ char smraw[];
    const int nt = blockIdx.x;
    const int bm = blockIdx.y * 128;
    if (nt < 8) {
        gemm_body(g_Xh, g_Wqh, /*bias via cast*/ nullptr, nullptr,
                  DM, DM, bm, nt * 128, 1, smraw);
    }
}

// NOTE: proj3 needs runtime bias pointers (harness inputs) -> pass as params.
__global__ __launch_bounds__(256, 2) void proj3_kernel_p(
    const float* __restrict__ b_q)
{
    extern __shared__ char smraw[];
    const int nt = blockIdx.x;
    const int bm = blockIdx.y * 128;
    if (nt < 8)
        gemm_body(g_Xh, g_Wqh, b_q, g_Qh, DM, DM, bm, nt * 128, 1, smraw);
    else
        gemm_body(g_Mh, g_WKVh, g_bkv, g_KVh, DM, KVSTR, bm, (nt - 8) * 128, 1, smraw);
}

// Output projection (separate: depends on attention result)
__global__ __launch_bounds__(256, 2) void gemm_o_kernel(
    const float* __restrict__ b_o, float* __restrict__ out)
{
    extern __shared__ char smraw[];
    gemm_body(g_Yh, g_Woh, b_o, out, DM, DM, blockIdx.y * 128, blockIdx.x * 128, 0, smraw);
}

// ---------------------------------------------------------------------------
// Flash attention v4 (unchanged R15 structure; K/V from fused KV buffer)
// ---------------------------------------------------------------------------
#define KC      64
#define QLDH    72
#define ATT_KS_BYTES (2 * KC * QLDH * 2)      // 18432
#define ATT_VS_BYTES (2 * KC * QLDH * 2)      // 18432
#define ATT_EX_OFF   (ATT_KS_BYTES + ATT_VS_BYTES)     // 36864
#define ATT_SMEM_BYTES (ATT_EX_OFF + 256 * 4)          // 37888
#define OLD     68    // obuf float stride
#define NJT     (TENC / KC)      // 32

__global__ __launch_bounds__(256, 2) void attn_kernel()
{
    extern __shared__ char smraw[];
    __half* Ks0 = reinterpret_cast<__half*>(smraw);                    // [2][KC x QLDH]
    __half* Vs0 = reinterpret_cast<__half*>(smraw + ATT_KS_BYTES);     // [2][KC x QLDH]
    float*  m_ex = reinterpret_cast<float*>(smraw + ATT_EX_OFF);       // [2][64]
    float*  l_ex = m_ex + 128;                                         // [2][64]
    float*  obuf = reinterpret_cast<float*>(smraw);                    // epilogue alias

    const __half* __restrict__ Q  = g_Qh;
    const __half* __restrict__ KV = g_KVh;
    __half* __restrict__ Y        = g_Yh;

    const int bh = blockIdx.y;
    const int b  = bh >> 4;
    const int h  = bh & 15;
    const int q0 = blockIdx.x * 64;
    const int tid = threadIdx.x;
    const int warp = tid >> 5;
    const int lane = tid & 31;
    const int g   = lane >> 2;
    const int tg  = lane & 3;
    const int wm = warp >> 1;           // pair id 0..3 -> 16-row stripe
    const int wn = warp & 1;            // 0..1 -> key half (split-K)
    const int R0 = wm * 16;
    const int C0 = wn * 32;

    const uint32_t vs_base = smem_addr_u32(Vs0);

    auto prefetch_kv = [&](int s, int jt) {
        __half* Ksb = Ks0 + s * KC * QLDH;
        __half* Vsb = Vs0 + s * KC * QLDH;
        const int j0 = jt * KC;
        #pragma unroll
        for (int i = tid; i < 1024; i += 256) {
            if (i < 512) {
                int row = i >> 3, c16 = i & 7;
                cp_async16(&Ksb[row * QLDH + c16 * 8],
                           &KV[(size_t)(b * TENC + j0 + row) * KVSTR + h * DH + c16 * 8]);
            } else {
                int j = i - 512;
                int row = j >> 3, c16 = j & 7;
                cp_async16(&Vsb[row * QLDH + c16 * 8],
                           &KV[(size_t)(b * TENC + j0 + row) * KVSTR + 1024 + h * DH + c16 * 8]);
            }
        }
        cp_commit();
    };

    // ---- Q A-fragments in registers (4 k16-tiles x 4 regs), scaled 0.125 ----
    uint32_t qa[4][4];
    {
        const __half2 sc2 = __float2half2_rn(0.125f);
        const __half* Qb = Q + (size_t)(b * TDEC + q0 + R0) * DM + h * DH;
        #pragma unroll
        for (int kt = 0; kt < 4; kt++) {
            __half2 v0 = *reinterpret_cast<const __half2*>(&Qb[(size_t)g * DM + 16 * kt + 2 * tg]);
            __half2 v1 = *reinterpret_cast<const __half2*>(&Qb[(size_t)(g + 8) * DM + 16 * kt + 2 * tg]);
            __half2 v2 = *reinterpret_cast<const __half2*>(&Qb[(size_t)g * DM + 16 * kt + 2 * tg + 8]);
            __half2 v3 = *reinterpret_cast<const __half2*>(&Qb[(size_t)(g + 8) * DM + 16 * kt + 2 * tg + 8]);
            v0 = __hmul2(v0, sc2); v1 = __hmul2(v1, sc2);
            v2 = __hmul2(v2, sc2); v3 = __hmul2(v3, sc2);
            qa[kt][0] = *reinterpret_cast<uint32_t*>(&v0);
            qa[kt][1] = *reinterpret_cast<uint32_t*>(&v1);
            qa[kt][2] = *reinterpret_cast<uint32_t*>(&v2);
            qa[kt][3] = *reinterpret_cast<uint32_t*>(&v3);
        }
    }

    float o[8][4];
    #pragma unroll
    for (int nt = 0; nt < 8; nt++)
        #pragma unroll
        for (int e = 0; e < 4; e++) o[nt][e] = 0.0f;
    float m0 = -1e30f, m1 = -1e30f, l0 = 0.0f, l1 = 0.0f;

    prefetch_kv(0, 0);

    for (int jt = 0; jt < NJT; jt++) {
        cp_wait_all();
        __syncthreads();
        if (jt + 1 < NJT) prefetch_kv((jt + 1) & 1, jt + 1);
        const int st = jt & 1;
        const __half* Ksb = Ks0 + st * KC * QLDH;
        const uint32_t vsst = vs_base + (uint32_t)(st * KC * QLDH * 2);

        // ---- S = Q K^T : 16 rows x 32 keys, in registers ----
        float s[4][4];
        #pragma unroll
        for (int j = 0; j < 4; j++)
            #pragma unroll
            for (int e = 0; e < 4; e++) s[j][e] = 0.0f;
        #pragma unroll
        for (int kt = 0; kt < 4; kt++) {
            #pragma unroll
            for (int j = 0; j < 4; j++) {
                uint32_t bb[2];
                const __half* Kr = &Ksb[(C0 + 8 * j + g) * QLDH + 16 * kt + 2 * tg];
                bb[0] = *reinterpret_cast<const uint32_t*>(&Kr[0]);
                bb[1] = *reinterpret_cast<const uint32_t*>(&Kr[8]);
                mma16n8k16(s[j], qa[kt], bb);
            }
        }

        // ---- split-K online softmax (rows R0+g, R0+8+g) ----
        {
            float px0 = -1e30f, px1 = -1e30f;
            #pragma unroll
            for (int j = 0; j < 4; j++) {
                px0 = fmaxf(px0, fmaxf(s[j][0], s[j][1]));
                px1 = fmaxf(px1, fmaxf(s[j][2], s[j][3]));
            }
            px0 = fmaxf(px0, __shfl_xor_sync(0xffffffffu, px0, 1));
            px0 = fmaxf(px0, __shfl_xor_sync(0xffffffffu, px0, 2));
            px1 = fmaxf(px1, __shfl_xor_sync(0xffffffffu, px1, 1));
            px1 = fmaxf(px1, __shfl_xor_sync(0xffffffffu, px1, 2));
            if (tg == 0) {
                m_ex[wn * 64 + R0 + g] = px0;
                m_ex[wn * 64 + R0 + 8 + g] = px1;
            }
            BAR_PAIR(wm + 1);
            const float mo0 = m_ex[(1 - wn) * 64 + R0 + g];
            const float mo1 = m_ex[(1 - wn) * 64 + R0 + 8 + g];
            const float m0n = fmaxf(m0, fmaxf(px0, mo0));
            const float m1n = fmaxf(m1, fmaxf(px1, mo1));
            const float al0 = __expf(m0 - m0n);
            const float al1 = __expf(m1 - m1n);
            float ps0 = 0.0f, ps1 = 0.0f;
            #pragma unroll
            for (int j = 0; j < 4; j++) {
                s[j][0] = __expf(s[j][0] - m0n);
                s[j][1] = __expf(s[j][1] - m0n);
                s[j][2] = __expf(s[j][2] - m1n);
                s[j][3] = __expf(s[j][3] - m1n);
                ps0 += s[j][0] + s[j][1];
                ps1 += s[j][2] + s[j][3];
            }
            ps0 += __shfl_xor_sync(0xffffffffu, ps0, 1);
            ps0 += __shfl_xor_sync(0xffffffffu, ps0, 2);
            ps1 += __shfl_xor_sync(0xffffffffu, ps1, 1);
            ps1 += __shfl_xor_sync(0xffffffffu, ps1, 2);
            if (tg == 0) {
                l_ex[wn * 64 + R0 + g] = ps0;
                l_ex[wn * 64 + R0 + 8 + g] = ps1;
            }
            BAR_PAIR(wm + 1);
            l0 = l0 * al0 + ps0 + l_ex[(1 - wn) * 64 + R0 + g];
            l1 = l1 * al1 + ps1 + l_ex[(1 - wn) * 64 + R0 + 8 + g];
            m0 = m0n; m1 = m1n;
            #pragma unroll
            for (int nt = 0; nt < 8; nt++) {
                o[nt][0] *= al0; o[nt][1] *= al0;
                o[nt][2] *= al1; o[nt][3] *= al1;
            }
        }

        // ---- O += P @ V over this warp's 32 keys; P = register repack ----
        {
            const int lrow = lane & 15;
            const int lcol = (lane >> 4) * 8;
            #pragma unroll
            for (int kt2 = 0; kt2 < 2; kt2++) {
                uint32_t a[4];
                a[0] = pack_h2(s[2 * kt2][0], s[2 * kt2][1]);
                a[1] = pack_h2(s[2 * kt2][2], s[2 * kt2][3]);
                a[2] = pack_h2(s[2 * kt2 + 1][0], s[2 * kt2 + 1][1]);
                a[3] = pack_h2(s[2 * kt2 + 1][2], s[2 * kt2 + 1][3]);
                const uint32_t va = vsst
                    + 2u * ((C0 + 16 * kt2 + lrow) * QLDH + lcol);
                #pragma unroll
                for (int n16 = 0; n16 < 4; n16++) {
                    uint32_t b0, b1, b2, b3;
                    ldmatrix_x4_trans(b0, b1, b2, b3, va + 2u * (16 * n16));
                    uint32_t bb0[2] = {b0, b1};
                    uint32_t bb1[2] = {b2, b3};
                    mma16n8k16(o[2 * n16 + 0], a, bb0);
                    mma16n8k16(o[2 * n16 + 1], a, bb1);
                }
            }
        }
    }
    __syncthreads();   // all K/V reads done; Ks area reusable as obuf

    // ---- pair-sum partial O, then write Y ----
    {
        float* ob = obuf + wm * 16 * OLD;
        if (wn == 0) {
            #pragma unroll
            for (int nt = 0; nt < 8; nt++) {
                ob[g * OLD + 8 * nt + 2 * tg]       = o[nt][0];
                ob[g * OLD + 8 * nt + 2 * tg + 1]   = o[nt][1];
                ob[(g + 8) * OLD + 8 * nt + 2 * tg]     = o[nt][2];
                ob[(g + 8) * OLD + 8 * nt + 2 * tg + 1] = o[nt][3];
            }
        }
        BAR_PAIR(wm + 1);
        if (wn == 1) {
            const float inv0 = 1.0f / l0;
            const float inv1 = 1.0f / l1;
            const size_t row_lo = (size_t)(b * TDEC + q0 + R0 + g) * DM + h * DH;
            const size_t row_hi = row_lo + (size_t)8 * DM;
            #pragma unroll
            for (int nt = 0; nt < 8; nt++) {
                const int c = 8 * nt + 2 * tg;
                float x0 = (o[nt][0] + ob[g * OLD + c]) * inv0;
                float x1 = (o[nt][1] + ob[g * OLD + c + 1]) * inv0;
                float x2 = (o[nt][2] + ob[(g + 8) * OLD + c]) * inv1;
                float x3 = (o[nt][3] + ob[(g + 8) * OLD + c + 1]) * inv1;
                __half2 vlo = __floats2half2_rn(x0, x1);
                __half2 vhi = __floats2half2_rn(x2, x3);
                *reinterpret_cast<__half2*>(&Y[row_lo + c]) = vlo;
                *reinterpret_cast<__half2*>(&Y[row_hi + c]) = vhi;
            }
        }
    }
}

// ---------------------------------------------------------------------------
// Launcher: 4 launches (convert, fused QKV proj, attention, O proj)
// ---------------------------------------------------------------------------
extern "C" void kernel_launch(void* const* d_in, const int* in_sizes, int n_in,
                              void* d_out, int out_size)
{
    const float* tgt    = (const float*)d_in[0];
    const float* memory = (const float*)d_in[1];
    const float* W_q    = (const float*)d_in[2];
    const float* b_q    = (const float*)d_in[3];
    const float* W_k    = (const float*)d_in[4];
    const float* b_k    = (const float*)d_in[5];
    const float* W_v    = (const float*)d_in[6];
    const float* b_v    = (const float*)d_in[7];
    const float* W_o    = (const float*)d_in[8];
    const float* b_o    = (const float*)d_in[9];
    float* out = (float*)d_out;

    cudaFuncSetAttribute(proj3_kernel_p, cudaFuncAttributeMaxDynamicSharedMemorySize,
                         GEMM_SMEM_BYTES);
    cudaFuncSetAttribute(gemm_o_kernel, cudaFuncAttributeMaxDynamicSharedMemorySize,
                         GEMM_SMEM_BYTES);
    cudaFuncSetAttribute(attn_kernel, cudaFuncAttributeMaxDynamicSharedMemorySize,
                         ATT_SMEM_BYTES);

    // 0: convert everything to fp16 (+ fused KV weight/bias concat)
    convert_all_kernel<<<2048, 256>>>(tgt, memory, W_q, W_k, W_v, W_o, b_k, b_v);
    // 1: fused Q/K/V projections (24 N-tiles x 32 M-tiles = 768 CTAs)
    proj3_kernel_p<<<dim3(24, 32), 256, GEMM_SMEM_BYTES>>>(b_q);
    // 2: attention
    attn_kernel<<<dim3(TDEC / 64, NB * NHEADS), 256, ATT_SMEM_BYTES>>>();
    // 3: output projection (fp32 out)
    gemm_o_kernel<<<dim3(DM / 128, BT / 128), 256, GEMM_SMEM_BYTES>>>(b_o, out);
}

// round 17
// speedup vs baseline: 4.5448x; 1.0877x over previous
#include <cuda_runtime.h>
#include <cuda_fp16.h>
#include <mma.h>
#include <cstdint>
using namespace nvcuda;

// Problem constants (fixed by the reference)
#define BT      4096      // B * T_dec = B * T_enc = 2 * 2048
#define DM      1024      // d_model
#define NHEADS  16
#define DH      64
#define TDEC    2048
#define TENC    2048
#define NB      2
#define KVSTR   2048      // fused KV buffer row stride (K cols 0-1023, V 1024-2047)

// Scratch (allocation-free)
__device__ __half g_Qh[BT * DM];
__device__ __half g_KVh[BT * KVSTR];   // fused K|V
__device__ __half g_Yh[BT * DM];
__device__ __half g_Xh[BT * DM];       // tgt, fp16
__device__ __half g_Mh[BT * DM];       // memory, fp16
__device__ __half g_Wqh[DM * DM];
__device__ __half g_WKVh[DM * KVSTR];  // fused W_k|W_v
__device__ __half g_Woh[DM * DM];
__device__ float  g_bkv[KVSTR];        // fused b_k|b_v

// ---------------------------------------------------------------------------
// helpers
// ---------------------------------------------------------------------------
__device__ __forceinline__ void cp_async16(void* smem_dst, const void* gmem_src) {
    unsigned sa = (unsigned)__cvta_generic_to_shared(smem_dst);
    asm volatile("cp.async.cg.shared.global [%0], [%1], 16;\n" :: "r"(sa), "l"(gmem_src));
}
__device__ __forceinline__ void cp_commit() {
    asm volatile("cp.async.commit_group;\n");
}
__device__ __forceinline__ void cp_wait_all() {
    asm volatile("cp.async.wait_group 0;\n");
}
__device__ __forceinline__ uint32_t smem_addr_u32(const void* p) {
    return (uint32_t)__cvta_generic_to_shared(p);
}
// PTX mma m16n8k16 fp16->fp32 (layouts verified R13-R16)
__device__ __forceinline__ void mma16n8k16(float* c, const uint32_t* a, const uint32_t* b) {
    asm volatile(
        "mma.sync.aligned.m16n8k16.row.col.f32.f16.f16.f32 "
        "{%0,%1,%2,%3}, {%4,%5,%6,%7}, {%8,%9}, {%0,%1,%2,%3};\n"
        : "+f"(c[0]), "+f"(c[1]), "+f"(c[2]), "+f"(c[3])
        : "r"(a[0]), "r"(a[1]), "r"(a[2]), "r"(a[3]), "r"(b[0]), "r"(b[1]));
}
__device__ __forceinline__ void ldmatrix_x4_trans(uint32_t& r0, uint32_t& r1,
                                                  uint32_t& r2, uint32_t& r3, uint32_t addr) {
    asm volatile("ldmatrix.sync.aligned.m8n8.x4.trans.shared.b16 {%0,%1,%2,%3}, [%4];"
                 : "=r"(r0), "=r"(r1), "=r"(r2), "=r"(r3) : "r"(addr));
}
__device__ __forceinline__ uint32_t pack_h2(float x, float y) {
    __half2 h = __floats2half2_rn(x, y);
    return *reinterpret_cast<uint32_t*>(&h);
}

// ---------------------------------------------------------------------------
// One-shot conversion: tgt, memory, W_q, W_k|W_v (concat), W_o  -> fp16,
// plus b_k|b_v concat (fp32).  Grid-stride over 12M floats.
// ---------------------------------------------------------------------------
__global__ void convert_all_kernel(
    const float* __restrict__ tgt, const float* __restrict__ mem,
    const float* __restrict__ Wq, const float* __restrict__ Wk,
    const float* __restrict__ Wv, const float* __restrict__ Wo,
    const float* __restrict__ bk, const float* __restrict__ bv)
{
    const int NA = BT * DM;     // 4M
    const int NW = DM * DM;     // 1M
    const int total4 = (2 * NA + 4 * NW) >> 2;
    for (int i = blockIdx.x * blockDim.x + threadIdx.x; i < total4;
         i += gridDim.x * blockDim.x) {
        int idx = i << 2;
        const float* s; __half* d;
        if (idx < NA)                    { s = tgt + idx; d = g_Xh + idx; }
        else if (idx < 2 * NA)           { s = mem + (idx - NA); d = g_Mh + (idx - NA); }
        else if (idx < 2 * NA + NW)      { s = Wq + (idx - 2 * NA); d = g_Wqh + (idx - 2 * NA); }
        else if (idx < 2 * NA + 2 * NW) {
            int l = idx - (2 * NA + NW);
            s = Wk + l;
            d = g_WKVh + ((l >> 10) << 11) + (l & 1023);          // K -> cols 0-1023
        } else if (idx < 2 * NA + 3 * NW) {
            int l = idx - (2 * NA + 2 * NW);
            s = Wv + l;
            d = g_WKVh + ((l >> 10) << 11) + (l & 1023) + 1024;   // V -> cols 1024-2047
        } else {
            int l = idx - (2 * NA + 3 * NW);
            s = Wo + l; d = g_Woh + l;
        }
        float4 v = *reinterpret_cast<const float4*>(s);
        __half2 h0 = __floats2half2_rn(v.x, v.y);
        __half2 h1 = __floats2half2_rn(v.z, v.w);
        uint2 u;
        u.x = *reinterpret_cast<uint32_t*>(&h0);
        u.y = *reinterpret_cast<uint32_t*>(&h1);
        *reinterpret_cast<uint2*>(d) = u;
    }
    if (blockIdx.x == 0 && threadIdx.x < 512) {
        int t = threadIdx.x * 4;
        float4 v = (t < 1024) ? *reinterpret_cast<const float4*>(bk + t)
                              : *reinterpret_cast<const float4*>(bv + (t - 1024));
        *reinterpret_cast<float4*>(g_bkv + t) = v;
    }
}

// ---------------------------------------------------------------------------
// Shared fp16 GEMM mainloop body (tile 128x128, BK=64, 8 warps, double-buffer)
// ---------------------------------------------------------------------------
#define GLDA 72     // 64 + 8 pad (halves)
#define GLDB 136    // 128 + 8 pad (halves)
#define GLDC 132    // 128 + 4 pad (floats)
#define A_STG (128 * GLDA)              // 9216 halves per A stage
#define B_STG (64 * GLDB)               // 8704 halves per B stage
#define GEMM_SMEM_BYTES ((2 * A_STG + 2 * B_STG) * 2)   // 71680 >= Cs 67584

__device__ __forceinline__ void gemm_body(
    const __half* __restrict__ X, const __half* __restrict__ W,
    const float* __restrict__ bias, void* __restrict__ Cout,
    int K, int N, int bm, int bn, int out_half, char* smraw)
{
    __half* As = reinterpret_cast<__half*>(smraw);
    __half* Bs = reinterpret_cast<__half*>(smraw + 2 * A_STG * 2);
    float*  Cs = reinterpret_cast<float*>(smraw);

    const int tid = threadIdx.x;
    const int warp = tid >> 5;
    const int wm = warp >> 1;
    const int wn = warp & 1;

    wmma::fragment<wmma::accumulator, 16, 16, 16, float> acc[2][4];
    #pragma unroll
    for (int i = 0; i < 2; i++)
        #pragma unroll
        for (int j = 0; j < 4; j++)
            wmma::fill_fragment(acc[i][j], 0.0f);

    auto load_stage = [&](int s, int k0) {
        #pragma unroll
        for (int i = tid; i < 1024; i += 256) {
            int row = i >> 3, c16 = i & 7;
            cp_async16(&As[s * A_STG + row * GLDA + c16 * 8],
                       &X[(size_t)(bm + row) * K + k0 + c16 * 8]);
        }
        #pragma unroll
        for (int i = tid; i < 1024; i += 256) {
            int row = i >> 4, c16 = i & 15;
            cp_async16(&Bs[s * B_STG + row * GLDB + c16 * 8],
                       &W[(size_t)(k0 + row) * N + bn + c16 * 8]);
        }
        cp_commit();
    };

    const int nk = K / 64;
    load_stage(0, 0);

    for (int kt = 0; kt < nk; kt++) {
        cp_wait_all();
        __syncthreads();
        if (kt + 1 < nk) load_stage((kt + 1) & 1, (kt + 1) * 64);
        const int s = kt & 1;

        #pragma unroll
        for (int kk = 0; kk < 64; kk += 16) {
            wmma::fragment<wmma::matrix_a, 16, 16, 16, __half, wmma::row_major> afr[2];
            wmma::fragment<wmma::matrix_b, 16, 16, 16, __half, wmma::row_major> bfr[4];
            #pragma unroll
            for (int mt = 0; mt < 2; mt++)
                wmma::load_matrix_sync(afr[mt],
                    &As[s * A_STG + (wm * 32 + mt * 16) * GLDA + kk], GLDA);
            #pragma unroll
            for (int nt = 0; nt < 4; nt++)
                wmma::load_matrix_sync(bfr[nt],
                    &Bs[s * B_STG + kk * GLDB + wn * 64 + nt * 16], GLDB);
            #pragma unroll
            for (int mt = 0; mt < 2; mt++)
                #pragma unroll
                for (int nt = 0; nt < 4; nt++)
                    wmma::mma_sync(acc[mt][nt], afr[mt], bfr[nt], acc[mt][nt]);
        }
    }

    __syncthreads();
    #pragma unroll
    for (int mt = 0; mt < 2; mt++)
        #pragma unroll
        for (int nt = 0; nt < 4; nt++)
            wmma::store_matrix_sync(
                &Cs[(size_t)(wm * 32 + mt * 16) * GLDC + wn * 64 + nt * 16],
                acc[mt][nt], GLDC, wmma::mem_row_major);
    __syncthreads();

    {
        const int row = tid >> 1;
        const int half_ = tid & 1;
        const float* src = &Cs[(size_t)row * GLDC + half_ * 64];
        const float* bsrc = &bias[bn + half_ * 64];
        if (out_half) {
            __half* dst = (__half*)Cout + (size_t)(bm + row) * N + bn + half_ * 64;
            #pragma unroll
            for (int j = 0; j < 64; j += 8) {
                uint4 u;
                __half2 h0 = __floats2half2_rn(src[j + 0] + bsrc[j + 0], src[j + 1] + bsrc[j + 1]);
                __half2 h1 = __floats2half2_rn(src[j + 2] + bsrc[j + 2], src[j + 3] + bsrc[j + 3]);
                __half2 h2 = __floats2half2_rn(src[j + 4] + bsrc[j + 4], src[j + 5] + bsrc[j + 5]);
                __half2 h3 = __floats2half2_rn(src[j + 6] + bsrc[j + 6], src[j + 7] + bsrc[j + 7]);
                u.x = *reinterpret_cast<uint32_t*>(&h0);
                u.y = *reinterpret_cast<uint32_t*>(&h1);
                u.z = *reinterpret_cast<uint32_t*>(&h2);
                u.w = *reinterpret_cast<uint32_t*>(&h3);
                *reinterpret_cast<uint4*>(&dst[j]) = u;
            }
        } else {
            float* dst = (float*)Cout + (size_t)(bm + row) * N + bn + half_ * 64;
            #pragma unroll
            for (int j = 0; j < 64; j += 4) {
                float4 v;
                v.x = src[j + 0] + bsrc[j + 0];
                v.y = src[j + 1] + bsrc[j + 1];
                v.z = src[j + 2] + bsrc[j + 2];
                v.w = src[j + 3] + bsrc[j + 3];
                *reinterpret_cast<float4*>(&dst[j]) = v;
            }
        }
    }
}

// Fused Q/K/V projection: grid.x = 8 (Q tiles) + 16 (KV tiles), grid.y = 32.
__global__ __launch_bounds__(256, 2) void proj3_kernel_p(
    const float* __restrict__ b_q)
{
    extern __shared__ char smraw[];
    const int nt = blockIdx.x;
    const int bm = blockIdx.y * 128;
    if (nt < 8)
        gemm_body(g_Xh, g_Wqh, b_q, g_Qh, DM, DM, bm, nt * 128, 1, smraw);
    else
        gemm_body(g_Mh, g_WKVh, g_bkv, g_KVh, DM, KVSTR, bm, (nt - 8) * 128, 1, smraw);
}

// Output projection (separate: depends on attention result)
__global__ __launch_bounds__(256, 2) void gemm_o_kernel(
    const float* __restrict__ b_o, float* __restrict__ out)
{
    extern __shared__ char smraw[];
    gemm_body(g_Yh, g_Woh, b_o, out, DM, DM, blockIdx.y * 128, blockIdx.x * 128, 0, smraw);
}

// ---------------------------------------------------------------------------
// Flash attention v5 (fp16): 128 Q rows/CTA, warp owns 16 FULL rows.
//  - warp-local softmax (intra-quad shfl only) -> no barriers, no stats smem
//  - 1 __syncthreads per KV chunk (stage handoff)
//  - Q/S/P/O in registers; K B-frags direct LDS; V via ldmatrix.trans
//  - direct register epilogue to Y (no pair-sum)
// grid = (TDEC/128, B*NHEADS) = (16, 32) = 512 CTAs; smem 36.9 KB; 2 CTAs/SM.
// ---------------------------------------------------------------------------
#define QT      128
#define KC      64
#define QLDH    72
#define ATT_KS_BYTES (2 * KC * QLDH * 2)      // 18432
#define ATT_SMEM_BYTES (2 * ATT_KS_BYTES)     // 36864
#define NJT     (TENC / KC)      // 32

__global__ __launch_bounds__(256, 2) void attn_kernel()
{
    extern __shared__ char smraw[];
    __half* Ks0 = reinterpret_cast<__half*>(smraw);                    // [2][KC x QLDH]
    __half* Vs0 = reinterpret_cast<__half*>(smraw + ATT_KS_BYTES);     // [2][KC x QLDH]

    const __half* __restrict__ Q  = g_Qh;
    const __half* __restrict__ KV = g_KVh;
    __half* __restrict__ Y        = g_Yh;

    const int bh = blockIdx.y;
    const int b  = bh >> 4;
    const int h  = bh & 15;
    const int q0 = blockIdx.x * QT;
    const int tid = threadIdx.x;
    const int warp = tid >> 5;
    const int lane = tid & 31;
    const int g   = lane >> 2;          // 0..7
    const int tg  = lane & 3;           // 0..3
    const int R0  = warp * 16;          // warp's 16-row stripe within CTA

    const uint32_t vs_base = smem_addr_u32(Vs0);

    auto prefetch_kv = [&](int s, int jt) {
        __half* Ksb = Ks0 + s * KC * QLDH;
        __half* Vsb = Vs0 + s * KC * QLDH;
        const int j0 = jt * KC;
        #pragma unroll
        for (int i = tid; i < 1024; i += 256) {
            if (i < 512) {
                int row = i >> 3, c16 = i & 7;
                cp_async16(&Ksb[row * QLDH + c16 * 8],
                           &KV[(size_t)(b * TENC + j0 + row) * KVSTR + h * DH + c16 * 8]);
            } else {
                int j = i - 512;
                int row = j >> 3, c16 = j & 7;
                cp_async16(&Vsb[row * QLDH + c16 * 8],
                           &KV[(size_t)(b * TENC + j0 + row) * KVSTR + 1024 + h * DH + c16 * 8]);
            }
        }
        cp_commit();
    };

    // ---- Q A-fragments in registers (4 k16-tiles x 4 regs), scaled 0.125 ----
    uint32_t qa[4][4];
    {
        const __half2 sc2 = __float2half2_rn(0.125f);
        const __half* Qb = Q + (size_t)(b * TDEC + q0 + R0) * DM + h * DH;
        #pragma unroll
        for (int kt = 0; kt < 4; kt++) {
            __half2 v0 = *reinterpret_cast<const __half2*>(&Qb[(size_t)g * DM + 16 * kt + 2 * tg]);
            __half2 v1 = *reinterpret_cast<const __half2*>(&Qb[(size_t)(g + 8) * DM + 16 * kt + 2 * tg]);
            __half2 v2 = *reinterpret_cast<const __half2*>(&Qb[(size_t)g * DM + 16 * kt + 2 * tg + 8]);
            __half2 v3 = *reinterpret_cast<const __half2*>(&Qb[(size_t)(g + 8) * DM + 16 * kt + 2 * tg + 8]);
            v0 = __hmul2(v0, sc2); v1 = __hmul2(v1, sc2);
            v2 = __hmul2(v2, sc2); v3 = __hmul2(v3, sc2);
            qa[kt][0] = *reinterpret_cast<uint32_t*>(&v0);
            qa[kt][1] = *reinterpret_cast<uint32_t*>(&v1);
            qa[kt][2] = *reinterpret_cast<uint32_t*>(&v2);
            qa[kt][3] = *reinterpret_cast<uint32_t*>(&v3);
        }
    }

    // O accumulator: 16 rows x 64 dh cols = 8 n8-tiles x 4 f32
    float o[8][4];
    #pragma unroll
    for (int nt = 0; nt < 8; nt++)
        #pragma unroll
        for (int e = 0; e < 4; e++) o[nt][e] = 0.0f;
    float m0 = -1e30f, m1 = -1e30f, l0 = 0.0f, l1 = 0.0f;

    prefetch_kv(0, 0);

    for (int jt = 0; jt < NJT; jt++) {
        cp_wait_all();
        __syncthreads();                 // stage jt&1 ready; prior stage reads done
        if (jt + 1 < NJT) prefetch_kv((jt + 1) & 1, jt + 1);
        const int st = jt & 1;
        const __half* Ksb = Ks0 + st * KC * QLDH;
        const uint32_t vsst = vs_base + (uint32_t)(st * KC * QLDH * 2);

        // ---- S = Q K^T : 16 rows x 64 keys, in registers ----
        float s[8][4];
        #pragma unroll
        for (int j = 0; j < 8; j++)
            #pragma unroll
            for (int e = 0; e < 4; e++) s[j][e] = 0.0f;
        #pragma unroll
        for (int kt = 0; kt < 4; kt++) {
            #pragma unroll
            for (int j = 0; j < 8; j++) {
                uint32_t bb[2];
                const __half* Kr = &Ksb[(8 * j + g) * QLDH + 16 * kt + 2 * tg];
                bb[0] = *reinterpret_cast<const uint32_t*>(&Kr[0]);
                bb[1] = *reinterpret_cast<const uint32_t*>(&Kr[8]);
                mma16n8k16(s[j], qa[kt], bb);
            }
        }

        // ---- warp-local online softmax (rows R0+g, R0+8+g) ----
        {
            float mx0 = -1e30f, mx1 = -1e30f;
            #pragma unroll
            for (int j = 0; j < 8; j++) {
                mx0 = fmaxf(mx0, fmaxf(s[j][0], s[j][1]));
                mx1 = fmaxf(mx1, fmaxf(s[j][2], s[j][3]));
            }
            mx0 = fmaxf(mx0, __shfl_xor_sync(0xffffffffu, mx0, 1));
            mx0 = fmaxf(mx0, __shfl_xor_sync(0xffffffffu, mx0, 2));
            mx1 = fmaxf(mx1, __shfl_xor_sync(0xffffffffu, mx1, 1));
            mx1 = fmaxf(mx1, __shfl_xor_sync(0xffffffffu, mx1, 2));
            const float m0n = fmaxf(m0, mx0);
            const float m1n = fmaxf(m1, mx1);
            const float al0 = __expf(m0 - m0n);
            const float al1 = __expf(m1 - m1n);
            float ps0 = 0.0f, ps1 = 0.0f;
            #pragma unroll
            for (int j = 0; j < 8; j++) {
                s[j][0] = __expf(s[j][0] - m0n);
                s[j][1] = __expf(s[j][1] - m0n);
                s[j][2] = __expf(s[j][2] - m1n);
                s[j][3] = __expf(s[j][3] - m1n);
                ps0 += s[j][0] + s[j][1];
                ps1 += s[j][2] + s[j][3];
            }
            ps0 += __shfl_xor_sync(0xffffffffu, ps0, 1);
            ps0 += __shfl_xor_sync(0xffffffffu, ps0, 2);
            ps1 += __shfl_xor_sync(0xffffffffu, ps1, 1);
            ps1 += __shfl_xor_sync(0xffffffffu, ps1, 2);
            l0 = l0 * al0 + ps0;
            l1 = l1 * al1 + ps1;
            m0 = m0n; m1 = m1n;
            #pragma unroll
            for (int nt = 0; nt < 8; nt++) {
                o[nt][0] *= al0; o[nt][1] *= al0;
                o[nt][2] *= al1; o[nt][3] *= al1;
            }
        }

        // ---- O += P @ V over all 64 keys; P = register repack of S ----
        {
            const int lrow = lane & 15;
            const int lcol = (lane >> 4) * 8;
            #pragma unroll
            for (int kt2 = 0; kt2 < 4; kt2++) {
                uint32_t a[4];
                a[0] = pack_h2(s[2 * kt2][0], s[2 * kt2][1]);
                a[1] = pack_h2(s[2 * kt2][2], s[2 * kt2][3]);
                a[2] = pack_h2(s[2 * kt2 + 1][0], s[2 * kt2 + 1][1]);
                a[3] = pack_h2(s[2 * kt2 + 1][2], s[2 * kt2 + 1][3]);
                const uint32_t va = vsst + 2u * ((16 * kt2 + lrow) * QLDH + lcol);
                #pragma unroll
                for (int n16 = 0; n16 < 4; n16++) {
                    uint32_t b0, b1, b2, b3;
                    ldmatrix_x4_trans(b0, b1, b2, b3, va + 2u * (16 * n16));
                    uint32_t bb0[2] = {b0, b1};
                    uint32_t bb1[2] = {b2, b3};
                    mma16n8k16(o[2 * n16 + 0], a, bb0);
                    mma16n8k16(o[2 * n16 + 1], a, bb1);
                }
            }
        }
    }

    // ---- Epilogue: direct register write of Y rows R0+g / R0+8+g ----
    {
        const float inv0 = 1.0f / l0;
        const float inv1 = 1.0f / l1;
        const size_t row_lo = (size_t)(b * TDEC + q0 + R0 + g) * DM + h * DH;
        const size_t row_hi = row_lo + (size_t)8 * DM;
        #pragma unroll
        for (int nt = 0; nt < 8; nt++) {
            const int c = 8 * nt + 2 * tg;
            __half2 vlo = __floats2half2_rn(o[nt][0] * inv0, o[nt][1] * inv0);
            __half2 vhi = __floats2half2_rn(o[nt][2] * inv1, o[nt][3] * inv1);
            *reinterpret_cast<__half2*>(&Y[row_lo + c]) = vlo;
            *reinterpret_cast<__half2*>(&Y[row_hi + c]) = vhi;
        }
    }
}

// ---------------------------------------------------------------------------
// Launcher: 4 launches (convert, fused QKV proj, attention, O proj)
// ---------------------------------------------------------------------------
extern "C" void kernel_launch(void* const* d_in, const int* in_sizes, int n_in,
                              void* d_out, int out_size)
{
    const float* tgt    = (const float*)d_in[0];
    const float* memory = (const float*)d_in[1];
    const float* W_q    = (const float*)d_in[2];
    const float* b_q    = (const float*)d_in[3];
    const float* W_k    = (const float*)d_in[4];
    const float* b_k    = (const float*)d_in[5];
    const float* W_v    = (const float*)d_in[6];
    const float* b_v    = (const float*)d_in[7];
    const float* W_o    = (const float*)d_in[8];
    const float* b_o    = (const float*)d_in[9];
    float* out = (float*)d_out;

    cudaFuncSetAttribute(proj3_kernel_p, cudaFuncAttributeMaxDynamicSharedMemorySize,
                         GEMM_SMEM_BYTES);
    cudaFuncSetAttribute(gemm_o_kernel, cudaFuncAttributeMaxDynamicSharedMemorySize,
                         GEMM_SMEM_BYTES);
    cudaFuncSetAttribute(attn_kernel, cudaFuncAttributeMaxDynamicSharedMemorySize,
                         ATT_SMEM_BYTES);

    // 0: convert everything to fp16 (+ fused KV weight/bias concat)
    convert_all_kernel<<<2048, 256>>>(tgt, memory, W_q, W_k, W_v, W_o, b_k, b_v);
    // 1: fused Q/K/V projections (24 N-tiles x 32 M-tiles = 768 CTAs)
    proj3_kernel_p<<<dim3(24, 32), 256, GEMM_SMEM_BYTES>>>(b_q);
    // 2: attention (512 CTAs)
    attn_kernel<<<dim3(TDEC / QT, NB * NHEADS), 256, ATT_SMEM_BYTES>>>();
    // 3: output projection (fp32 out)
    gemm_o_kernel<<<dim3(DM / 128, BT / 128), 256, GEMM_SMEM_BYTES>>>(b_o, out);
}